// round 11
// baseline (speedup 1.0000x reference)
#include <cuda_runtime.h>
#include <cstdint>

#define BATCH 8
#define NPTS  32768
#define SPTS  512
#define GRP   32
#define BIGF  1e10f
#define R2F   0.04f

#define CLUSTER      8
#define FPS_THREADS  128
#define FPS_NWARP    (FPS_THREADS / 32)      // 4
#define PTS_BLK      (NPTS / CLUSTER)        // 4096
#define PPT          (PTS_BLK / FPS_THREADS) // 32
#define NP2          (PPT / 2)               // 16 packed slots

#define CPT        32
#define BQ_THREADS 256
#define CAP        128

#define COMB_ELEMS (BATCH * SPTS * (GRP + 1) * 3)  // 405504

__device__ float4 g_xyz4[BATCH * NPTS];

// ---------------------------------------------------------------------------
// helpers
// ---------------------------------------------------------------------------
__device__ __forceinline__ unsigned smem_u32(const void* p) {
    unsigned a;
    asm("{ .reg .u64 t; cvta.to.shared.u64 t, %1; cvt.u32.u64 %0, t; }" : "=r"(a) : "l"(p));
    return a;
}
__device__ __forceinline__ unsigned redux_max_u32(unsigned v) {
    unsigned r; asm("redux.sync.max.u32 %0, %1, 0xffffffff;" : "=r"(r) : "r"(v)); return r;
}
__device__ __forceinline__ unsigned redux_min_u32(unsigned v) {
    unsigned r; asm("redux.sync.min.u32 %0, %1, 0xffffffff;" : "=r"(r) : "r"(v)); return r;
}
__device__ __forceinline__ unsigned mapa_u32(unsigned laddr, unsigned rank) {
    unsigned r; asm("mapa.shared::cluster.u32 %0, %1, %2;" : "=r"(r) : "r"(laddr), "r"(rank));
    return r;
}

// packed f32x2 (Blackwell): IEEE rn per component — bit-identical to scalar rn
#define PACK2(d, lo, hi)  asm("mov.b64 %0, {%1, %2};" : "=l"(d) : "f"(lo), "f"(hi))
#define UNPACK2(lo, hi, s) asm("mov.b64 {%0, %1}, %2;" : "=f"(lo), "=f"(hi) : "l"(s))
#define ADD2(d, a, b) asm("add.rn.f32x2 %0, %1, %2;" : "=l"(d) : "l"(a), "l"(b))
#define MUL2(d, a, b) asm("mul.rn.f32x2 %0, %1, %2;" : "=l"(d) : "l"(a), "l"(b))

__device__ __forceinline__ float negf(float a) {
    return __uint_as_float(__float_as_uint(a) ^ 0x80000000u);
}

#define MBAR_INIT(addr, cnt) \
    asm volatile("mbarrier.init.shared.b64 [%0], %1;" :: "r"(addr), "r"(cnt) : "memory")

#define MBAR_EXPECT_TX(addr, bytes) \
    asm volatile("mbarrier.arrive.expect_tx.shared.b64 _, [%0], %1;" \
                 :: "r"(addr), "r"(bytes) : "memory")

// fused data + barrier-signal store to a peer CTA's smem (single fabric hop)
#define ST_ASYNC_U64(rslot, val, rbar) \
    asm volatile("st.async.shared::cluster.mbarrier::complete_tx::bytes.b64 [%0], %1, [%2];" \
                 :: "r"(rslot), "l"(val), "r"(rbar) : "memory")

#define MBAR_WAIT_PARITY_ACQ_CLUSTER(mbar, parity) do {                            \
    unsigned _m = (mbar), _p = (parity), _d;                                       \
    asm volatile("{\n\t.reg .pred p;\n\t"                                          \
        "mbarrier.try_wait.parity.acquire.cluster.shared::cta.b64 p, [%1], %2;\n\t"\
        "selp.b32 %0, 1, 0, p;\n\t}"                                               \
        : "=r"(_d) : "r"(_m), "r"(_p) : "memory");                                 \
    if (!_d) {                                                                     \
        asm volatile("{\n\t.reg .pred P1;\n"                                       \
            "WL_%=:\n\t"                                                           \
            "mbarrier.try_wait.parity.acquire.cluster.shared::cta.b64 P1, [%0], %1;\n\t" \
            "@P1 bra.uni WD_%=;\n\t"                                               \
            "bra.uni WL_%=;\n"                                                     \
            "WD_%=:\n\t}" :: "r"(_m), "r"(_p) : "memory");                         \
    }                                                                              \
} while (0)

#define CLUSTER_SYNC_ASM() do {                                        \
    asm volatile("barrier.cluster.arrive.aligned;" ::: "memory");      \
    asm volatile("barrier.cluster.wait.aligned;" ::: "memory");        \
} while (0)

// ---------------------------------------------------------------------------
// Kernel 0: pack xyz [B,N,3] -> float4
// ---------------------------------------------------------------------------
__global__ void pad_kernel(const float* __restrict__ xyz) {
    int i = blockIdx.x * blockDim.x + threadIdx.x;
    if (i < BATCH * NPTS) {
        g_xyz4[i] = make_float4(xyz[3 * i], xyz[3 * i + 1], xyz[3 * i + 2], 0.f);
    }
}

// ---------------------------------------------------------------------------
// Kernel 1: FPS — R10 structure (st.async fused exchange) + coords carried
// through the exchange as extra parallel st.async words: the dependent
// winner-coord L2 load is replaced by a broadcast LDS.
// Exchange slot per CTA: [key = dist<<32|pid, xy = pack(x,y), zw = z]
// expect_tx per phase: 24 bytes x 8 CTAs = 192.
// ---------------------------------------------------------------------------
struct __align__(8) WSlot { unsigned long long key, xy, zw; };

__global__ void __cluster_dims__(CLUSTER, 1, 1) __launch_bounds__(FPS_THREADS, 1)
fps_kernel(const int* __restrict__ finit, float* __restrict__ out_cent) {
    const int tid  = threadIdx.x;
    const int lane = tid & 31, wid = tid >> 5;
    unsigned rank;
    asm("mov.u32 %0, %%cluster_ctarank;" : "=r"(rank));
    const int b = blockIdx.x / CLUSTER;
    const float4* __restrict__ xb = g_xyz4 + b * NPTS;

    __shared__ WSlot wslot[FPS_NWARP];                     // block-stage winners
    __shared__ unsigned long long cslot[2][CLUSTER][3];    // cluster-stage winners
    __shared__ unsigned long long bars[2];

    if (tid == 0) {
        MBAR_INIT(smem_u32(&bars[0]), 1);
        MBAR_INIT(smem_u32(&bars[1]), 1);
        MBAR_EXPECT_TX(smem_u32(&bars[0]), 24u * CLUSTER);
        MBAR_EXPECT_TX(smem_u32(&bars[1]), 24u * CLUSTER);
    }
    __syncthreads();
    CLUSTER_SYNC_ASM();   // init+arm visible cluster-wide before any st.async

    // register-resident points, packed pairs: slot j = points (2j, 2j+1),
    // point i lives at pid0 + i*FPS_THREADS; pid&127 = tid, (pid>>7)&31 = i
    unsigned long long pxx[NP2], pyy[NP2], pzz[NP2];
    float dd[PPT];
    const int pid0 = rank * PTS_BLK + tid;
#pragma unroll
    for (int j = 0; j < NP2; j++) {
        float4 a = xb[pid0 + (2 * j) * FPS_THREADS];
        float4 c = xb[pid0 + (2 * j + 1) * FPS_THREADS];
        PACK2(pxx[j], a.x, c.x);
        PACK2(pyy[j], a.y, c.y);
        PACK2(pzz[j], a.z, c.z);
        dd[2 * j] = BIGF; dd[2 * j + 1] = BIGF;
    }

    float4 c0 = xb[finit[b]];
    float cx = c0.x, cy = c0.y, cz = c0.z;

    for (int s = 0; s < SPTS; s++) {
        if (rank == 0 && tid == 0) {
            float* o = out_cent + (size_t)(b * SPTS + s) * 3;
            o[0] = cx; o[1] = cy; o[2] = cz;
        }
        if (s == SPTS - 1) break;

        // ---- packed distance update: (p - c)^2 as p + (-c), exact rn ----
        unsigned long long ncx2, ncy2, ncz2;
        {
            float nx = negf(cx), ny = negf(cy), nz = negf(cz);
            PACK2(ncx2, nx, nx); PACK2(ncy2, ny, ny); PACK2(ncz2, nz, nz);
        }
#pragma unroll
        for (int j = 0; j < NP2; j++) {
            unsigned long long dx2, dy2, dz2, s2;
            ADD2(dx2, pxx[j], ncx2);
            ADD2(dy2, pyy[j], ncy2);
            ADD2(dz2, pzz[j], ncz2);
            MUL2(dx2, dx2, dx2);
            MUL2(dy2, dy2, dy2);
            MUL2(dz2, dz2, dz2);
            ADD2(s2, dx2, dy2);
            ADD2(s2, s2, dz2);
            float lo, hi; UNPACK2(lo, hi, s2);
            dd[2 * j]     = fminf(dd[2 * j], lo);
            dd[2 * j + 1] = fminf(dd[2 * j + 1], hi);
        }

        // ---- thread argmax: fmax tree + equality bitmask (lowest i wins) ----
        float t16[16];
#pragma unroll
        for (int i = 0; i < 16; i++) t16[i] = fmaxf(dd[i], dd[i + 16]);
        float t8[8];
#pragma unroll
        for (int i = 0; i < 8; i++) t8[i] = fmaxf(t16[i], t16[i + 8]);
        float t4a = fmaxf(t8[0], t8[4]), t4b = fmaxf(t8[1], t8[5]);
        float t4c = fmaxf(t8[2], t8[6]), t4d = fmaxf(t8[3], t8[7]);
        float bv = fmaxf(fmaxf(t4a, t4b), fmaxf(t4c, t4d));
        unsigned m = 0;
#pragma unroll
        for (int i = 0; i < PPT; i++) m |= (dd[i] == bv) ? (1u << i) : 0u;
        int bi = __ffs(m) - 1;
        unsigned bpid = (unsigned)(pid0 + bi * FPS_THREADS);

        // ---- per-lane coord extraction of own best point (parallel) ----
        unsigned long long oxy, ozw;
        {
            int jj = bi >> 1, h = bi & 1;
            unsigned long long xx = pxx[0], yy = pyy[0], zz = pzz[0];
#pragma unroll
            for (int q = 1; q < NP2; q++)
                if (jj == q) { xx = pxx[q]; yy = pyy[q]; zz = pzz[q]; }
            float xl, xh, yl, yh, zl, zh;
            UNPACK2(xl, xh, xx); UNPACK2(yl, yh, yy); UNPACK2(zl, zh, zz);
            float ox = h ? xh : xl, oy = h ? yh : yl, oz = h ? zh : zl;
            PACK2(oxy, ox, oy);
            ozw = (unsigned long long)__float_as_uint(oz);
        }

        // ---- warp argmax via REDUX (tie -> smaller pid) ----
        unsigned vb   = __float_as_uint(bv);
        unsigned vmax = redux_max_u32(vb);
        unsigned pidw = redux_min_u32((vb == vmax) ? bpid : 0xffffffffu);

        // owner lane writes warp slot directly (no shuffles)
        if ((pidw & 127u) == (unsigned)tid) {
            wslot[wid].key = ((unsigned long long)vmax << 32) | pidw;
            wslot[wid].xy  = oxy;
            wslot[wid].zw  = ozw;
        }
        __syncthreads();

        const int bb = s & 1;
        const unsigned ph = (unsigned)((s >> 1) & 1);

        // ---- warp0: block reduce over 4 warp slots, fused publish to 8 CTAs ----
        if (wid == 0) {
            unsigned long long k = (lane < FPS_NWARP) ? wslot[lane].key : 0ull;
            unsigned v   = (unsigned)(k >> 32);
            unsigned pid = (unsigned)k;
            unsigned vm2 = redux_max_u32((lane < FPS_NWARP) ? v : 0u);
            unsigned pm2 = redux_min_u32((lane < FPS_NWARP && v == vm2) ? pid : 0xffffffffu);
            unsigned msk = __ballot_sync(0xffffffffu,
                                         lane < FPS_NWARP && pid == pm2 && v == vm2);
            int src = __ffs(msk) - 1;
            if (lane < CLUSTER) {
                unsigned long long key = ((unsigned long long)vm2 << 32) | pm2;
                unsigned long long xy  = wslot[src].xy;
                unsigned long long zw  = wslot[src].zw;
                unsigned rbase = mapa_u32(smem_u32(&cslot[bb][rank][0]), (unsigned)lane);
                unsigned rbar  = mapa_u32(smem_u32(&bars[bb]), (unsigned)lane);
                ST_ASYNC_U64(rbase,       key, rbar);
                ST_ASYNC_U64(rbase + 8u,  xy,  rbar);
                ST_ASYNC_U64(rbase + 16u, zw,  rbar);
            }
        }

        // ---- every warp: wait for 8 CTA candidates, reduce locally ----
        MBAR_WAIT_PARITY_ACQ_CLUSTER(smem_u32(&bars[bb]), ph);

        // re-arm this barrier for its next use (iteration s+2); safe: any s+2
        // store needs our s+1 publish, which is program-ordered after this.
        if (tid == 0)
            MBAR_EXPECT_TX(smem_u32(&bars[bb]), 24u * CLUSTER);

        unsigned long long ck = (lane < CLUSTER) ? cslot[bb][lane][0] : 0ull;
        unsigned cv  = (unsigned)(ck >> 32);
        unsigned cp  = (unsigned)ck;
        unsigned cvm = redux_max_u32((lane < CLUSTER) ? cv : 0u);
        unsigned cpm = redux_min_u32((lane < CLUSTER && cv == cvm) ? cp : 0xffffffffu);
        unsigned m3  = __ballot_sync(0xffffffffu, lane < CLUSTER && cp == cpm && cv == cvm);
        int src3 = __ffs(m3) - 1;

        // winner coords from local smem (broadcast LDS, no L2 dependency)
        unsigned long long wxy = cslot[bb][src3][1];
        unsigned long long wzw = cslot[bb][src3][2];
        cx = __uint_as_float((unsigned)wxy);
        cy = __uint_as_float((unsigned)(wxy >> 32));
        cz = __uint_as_float((unsigned)wzw);
    }

    CLUSTER_SYNC_ASM();
}

// ---------------------------------------------------------------------------
// Kernel 2: ball query + group — packed f32x2 main loop (proven R5/R6 version).
// ---------------------------------------------------------------------------
__global__ void __launch_bounds__(BQ_THREADS, 1)
ball_kernel(const float* __restrict__ cent, float* __restrict__ outc) {
    const int b  = blockIdx.x >> 4;
    const int s0 = (blockIdx.x & 15) * CPT;
    const int tid = threadIdx.x;
    const int lane = tid & 31, wid = tid >> 5;

    __shared__ float4 sc[CPT];
    __shared__ int cnt[CPT];
    __shared__ unsigned long long keys[CPT][CAP];
    __shared__ int sel[CPT][GRP];

    if (tid < CPT) {
        cnt[tid] = 0;
        const float* c = cent + (size_t)(b * SPTS + s0 + tid) * 3;
        sc[tid] = make_float4(c[0], c[1], c[2], 0.f);
    }
    __syncthreads();

    unsigned long long ncx2[CPT / 2], ncy2[CPT / 2], ncz2[CPT / 2];
#pragma unroll
    for (int j = 0; j < CPT / 2; j++) {
        float4 a = sc[2 * j], c = sc[2 * j + 1];
        PACK2(ncx2[j], negf(a.x), negf(c.x));
        PACK2(ncy2[j], negf(a.y), negf(c.y));
        PACK2(ncz2[j], negf(a.z), negf(c.z));
    }

    const float4* __restrict__ xb = g_xyz4 + b * NPTS;

    for (int pid = tid; pid < NPTS; pid += BQ_THREADS) {
        float4 p = xb[pid];
        unsigned long long px2, py2, pz2;
        PACK2(px2, p.x, p.x); PACK2(py2, p.y, p.y); PACK2(pz2, p.z, p.z);
#pragma unroll
        for (int j = 0; j < CPT / 2; j++) {
            unsigned long long dx2, dy2, dz2, s2;
            ADD2(dx2, px2, ncx2[j]);
            ADD2(dy2, py2, ncy2[j]);
            ADD2(dz2, pz2, ncz2[j]);
            MUL2(dx2, dx2, dx2);
            MUL2(dy2, dy2, dy2);
            MUL2(dz2, dz2, dz2);
            ADD2(s2, dx2, dy2);
            ADD2(s2, s2, dz2);
            float lo, hi; UNPACK2(lo, hi, s2);
            if (lo <= R2F) {
                int pos = atomicAdd(&cnt[2 * j], 1);
                if (pos < CAP)
                    keys[2 * j][pos] = ((unsigned long long)__float_as_uint(lo) << 32) | (unsigned)pid;
            }
            if (hi <= R2F) {
                int pos = atomicAdd(&cnt[2 * j + 1], 1);
                if (pos < CAP)
                    keys[2 * j + 1][pos] = ((unsigned long long)__float_as_uint(hi) << 32) | (unsigned)pid;
            }
        }
    }
    __syncthreads();

    for (int k = 0; k < CPT / 8; k++) {
        const int c = wid * (CPT / 8) + k;
        const int m = min(cnt[c], CAP);
        const int K = min(m, GRP);

        unsigned long long kk[CAP / 32];
#pragma unroll
        for (int j = 0; j < CAP / 32; j++) {
            int pos = lane + 32 * j;
            kk[j] = (pos < m) ? keys[c][pos] : 0xFFFFFFFFFFFFFFFFull;
        }
        for (int t = 0; t < K; t++) {
            unsigned long long lm = kk[0];
#pragma unroll
            for (int j = 1; j < CAP / 32; j++) lm = (kk[j] < lm) ? kk[j] : lm;
#pragma unroll
            for (int off = 16; off; off >>= 1) {
                unsigned long long o = __shfl_xor_sync(0xffffffffu, lm, off);
                lm = (o < lm) ? o : lm;
            }
#pragma unroll
            for (int j = 0; j < CAP / 32; j++) if (kk[j] == lm) kk[j] = 0xFFFFFFFFFFFFFFFFull;
            if (lane == 0) sel[c][t] = (int)(unsigned)(lm & 0xFFFFFFFFull);
        }

        float ccx, ccy, ccz;
        { float4 t4 = sc[c]; ccx = t4.x; ccy = t4.y; ccz = t4.z; }
        int need = GRP - K;
        int base = 0;
        while (need > 0) {
            int id = base + lane;
            bool oor = false;
            if (id < NPTS) {
                float4 p = xb[id];
                float dx = p.x - ccx, dy = p.y - ccy, dz = p.z - ccz;
                float sq = __fadd_rn(__fadd_rn(__fmul_rn(dx, dx), __fmul_rn(dy, dy)),
                                     __fmul_rn(dz, dz));
                oor = (sq > R2F);
            }
            unsigned msk = __ballot_sync(0xffffffffu, oor);
            int r = __popc(msk & ((1u << lane) - 1u));
            if (oor && r < need) sel[c][GRP - need + r] = id;
            int take = min(__popc(msk), need);
            need -= take;
            base += 32;
        }
    }
    __syncthreads();

    for (int k = 0; k < CPT / 8; k++) {
        const int c = wid * (CPT / 8) + k;
        const int s = s0 + c;
        float4 cc = sc[c];
        float* ob = outc + (size_t)((b * SPTS + s) * (GRP + 1)) * 3;
        if (lane == 0) { ob[0] = cc.x; ob[1] = cc.y; ob[2] = cc.z; }
        int idx = sel[c][lane];
        float4 p = xb[idx];
        float* og = ob + (size_t)(1 + lane) * 3;
        og[0] = p.x - cc.x; og[1] = p.y - cc.y; og[2] = p.z - cc.z;
    }
}

// ---------------------------------------------------------------------------
extern "C" void kernel_launch(void* const* d_in, const int* in_sizes, int n_in,
                              void* d_out, int out_size) {
    const float* xyz   = (const float*)d_in[0];
    const int*   finit = (const int*)d_in[1];
    float* out  = (float*)d_out;
    float* comb = out;                 // [B,S,33,3]
    float* cent = out + COMB_ELEMS;    // [B,S,3]

    pad_kernel<<<(BATCH * NPTS + 255) / 256, 256>>>(xyz);
    fps_kernel<<<BATCH * CLUSTER, FPS_THREADS>>>(finit, cent);
    ball_kernel<<<BATCH * (SPTS / CPT), BQ_THREADS>>>(cent, comb);
}

// round 12
// speedup vs baseline: 1.1827x; 1.1827x over previous
#include <cuda_runtime.h>
#include <cstdint>

#define BATCH 8
#define NPTS  32768
#define SPTS  512
#define GRP   32
#define BIGF  1e10f
#define R2F   0.04f

#define CLUSTER      8
#define FPS_THREADS  128
#define FPS_NWARP    (FPS_THREADS / 32)      // 4
#define NSLOT        (CLUSTER * FPS_NWARP)   // 32
#define PTS_BLK      (NPTS / CLUSTER)        // 4096
#define PPT          (PTS_BLK / FPS_THREADS) // 32
#define NP2          (PPT / 2)               // 16 packed slots

#define CPT        32
#define BQ_THREADS 256
#define CAP        128

#define COMB_ELEMS (BATCH * SPTS * (GRP + 1) * 3)  // 405504

__device__ float4 g_xyz4[BATCH * NPTS];

// ---------------------------------------------------------------------------
// helpers
// ---------------------------------------------------------------------------
__device__ __forceinline__ unsigned smem_u32(const void* p) {
    unsigned a;
    asm("{ .reg .u64 t; cvta.to.shared.u64 t, %1; cvt.u32.u64 %0, t; }" : "=r"(a) : "l"(p));
    return a;
}
__device__ __forceinline__ unsigned redux_max_u32(unsigned v) {
    unsigned r; asm("redux.sync.max.u32 %0, %1, 0xffffffff;" : "=r"(r) : "r"(v)); return r;
}
__device__ __forceinline__ unsigned redux_min_u32(unsigned v) {
    unsigned r; asm("redux.sync.min.u32 %0, %1, 0xffffffff;" : "=r"(r) : "r"(v)); return r;
}
__device__ __forceinline__ unsigned mapa_u32(unsigned laddr, unsigned rank) {
    unsigned r; asm("mapa.shared::cluster.u32 %0, %1, %2;" : "=r"(r) : "r"(laddr), "r"(rank));
    return r;
}

// packed f32x2 (Blackwell): IEEE rn per component — bit-identical to scalar rn
#define PACK2(d, lo, hi)  asm("mov.b64 %0, {%1, %2};" : "=l"(d) : "f"(lo), "f"(hi))
#define UNPACK2(lo, hi, s) asm("mov.b64 {%0, %1}, %2;" : "=f"(lo), "=f"(hi) : "l"(s))
#define ADD2(d, a, b) asm("add.rn.f32x2 %0, %1, %2;" : "=l"(d) : "l"(a), "l"(b))
#define MUL2(d, a, b) asm("mul.rn.f32x2 %0, %1, %2;" : "=l"(d) : "l"(a), "l"(b))

__device__ __forceinline__ float negf(float a) {
    return __uint_as_float(__float_as_uint(a) ^ 0x80000000u);
}

#define MBAR_INIT(addr, cnt) \
    asm volatile("mbarrier.init.shared.b64 [%0], %1;" :: "r"(addr), "r"(cnt) : "memory")

#define MBAR_EXPECT_TX(addr, bytes) \
    asm volatile("mbarrier.arrive.expect_tx.shared.b64 _, [%0], %1;" \
                 :: "r"(addr), "r"(bytes) : "memory")

// fused data + barrier-signal store to a peer CTA's smem (single fabric hop)
#define ST_ASYNC_U64(rslot, val, rbar) \
    asm volatile("st.async.shared::cluster.mbarrier::complete_tx::bytes.b64 [%0], %1, [%2];" \
                 :: "r"(rslot), "l"(val), "r"(rbar) : "memory")

#define MBAR_WAIT_PARITY_ACQ_CLUSTER(mbar, parity) do {                            \
    unsigned _m = (mbar), _p = (parity), _d;                                       \
    asm volatile("{\n\t.reg .pred p;\n\t"                                          \
        "mbarrier.try_wait.parity.acquire.cluster.shared::cta.b64 p, [%1], %2;\n\t"\
        "selp.b32 %0, 1, 0, p;\n\t}"                                               \
        : "=r"(_d) : "r"(_m), "r"(_p) : "memory");                                 \
    if (!_d) {                                                                     \
        asm volatile("{\n\t.reg .pred P1;\n"                                       \
            "WL_%=:\n\t"                                                           \
            "mbarrier.try_wait.parity.acquire.cluster.shared::cta.b64 P1, [%0], %1;\n\t" \
            "@P1 bra.uni WD_%=;\n\t"                                               \
            "bra.uni WL_%=;\n"                                                     \
            "WD_%=:\n\t}" :: "r"(_m), "r"(_p) : "memory");                         \
    }                                                                              \
} while (0)

#define CLUSTER_SYNC_ASM() do {                                        \
    asm volatile("barrier.cluster.arrive.aligned;" ::: "memory");      \
    asm volatile("barrier.cluster.wait.aligned;" ::: "memory");        \
} while (0)

// ---------------------------------------------------------------------------
// Kernel 0: pack xyz [B,N,3] -> float4
// ---------------------------------------------------------------------------
__global__ void pad_kernel(const float* __restrict__ xyz) {
    int i = blockIdx.x * blockDim.x + threadIdx.x;
    if (i < BATCH * NPTS) {
        g_xyz4[i] = make_float4(xyz[3 * i], xyz[3 * i + 1], xyz[3 * i + 2], 0.f);
    }
}

// ---------------------------------------------------------------------------
// Kernel 1: FPS — flat st.async exchange: every warp publishes its winner key
// to all 8 CTAs (slot = rank*4 + wid); no __syncthreads, no block stage.
// Receiver: 32 slots = 32 lanes, one redux pair, uniform L2 winner-coord load.
// expect_tx per phase: 8 bytes x 32 warps = 256.
// ---------------------------------------------------------------------------
__global__ void __cluster_dims__(CLUSTER, 1, 1) __launch_bounds__(FPS_THREADS, 1)
fps_kernel(const int* __restrict__ finit, float* __restrict__ out_cent) {
    const int tid  = threadIdx.x;
    const int lane = tid & 31, wid = tid >> 5;
    unsigned rank;
    asm("mov.u32 %0, %%cluster_ctarank;" : "=r"(rank));
    const int b = blockIdx.x / CLUSTER;
    const float4* __restrict__ xb = g_xyz4 + b * NPTS;

    __shared__ unsigned long long cslot[2][NSLOT];   // 32 warp winners (dbl buf)
    __shared__ unsigned long long bars[2];

    if (tid == 0) {
        MBAR_INIT(smem_u32(&bars[0]), 1);
        MBAR_INIT(smem_u32(&bars[1]), 1);
        MBAR_EXPECT_TX(smem_u32(&bars[0]), 8u * NSLOT);
        MBAR_EXPECT_TX(smem_u32(&bars[1]), 8u * NSLOT);
    }
    __syncthreads();
    CLUSTER_SYNC_ASM();   // init+arm visible cluster-wide before any st.async

    // register-resident points, packed pairs: slot j = points (2j, 2j+1),
    // point i lives at pid0 + i*FPS_THREADS
    unsigned long long pxx[NP2], pyy[NP2], pzz[NP2];
    float dd[PPT];
    const int pid0 = rank * PTS_BLK + tid;
#pragma unroll
    for (int j = 0; j < NP2; j++) {
        float4 a = xb[pid0 + (2 * j) * FPS_THREADS];
        float4 c = xb[pid0 + (2 * j + 1) * FPS_THREADS];
        PACK2(pxx[j], a.x, c.x);
        PACK2(pyy[j], a.y, c.y);
        PACK2(pzz[j], a.z, c.z);
        dd[2 * j] = BIGF; dd[2 * j + 1] = BIGF;
    }

    // per-warp publish addresses: lane r (<8) targets rank r, slot rank*4+wid
    const unsigned lslot0 = smem_u32(&cslot[0][rank * FPS_NWARP + wid]);
    const unsigned lslot1 = smem_u32(&cslot[1][rank * FPS_NWARP + wid]);
    const unsigned lbar0  = smem_u32(&bars[0]);
    const unsigned lbar1  = smem_u32(&bars[1]);

    float4 c0 = xb[finit[b]];
    float cx = c0.x, cy = c0.y, cz = c0.z;

    for (int s = 0; s < SPTS; s++) {
        if (rank == 0 && tid == 0) {
            float* o = out_cent + (size_t)(b * SPTS + s) * 3;
            o[0] = cx; o[1] = cy; o[2] = cz;
        }
        if (s == SPTS - 1) break;

        // ---- packed distance update: (p - c)^2 as p + (-c), exact rn ----
        unsigned long long ncx2, ncy2, ncz2;
        {
            float nx = negf(cx), ny = negf(cy), nz = negf(cz);
            PACK2(ncx2, nx, nx); PACK2(ncy2, ny, ny); PACK2(ncz2, nz, nz);
        }
#pragma unroll
        for (int j = 0; j < NP2; j++) {
            unsigned long long dx2, dy2, dz2, s2;
            ADD2(dx2, pxx[j], ncx2);
            ADD2(dy2, pyy[j], ncy2);
            ADD2(dz2, pzz[j], ncz2);
            MUL2(dx2, dx2, dx2);
            MUL2(dy2, dy2, dy2);
            MUL2(dz2, dz2, dz2);
            ADD2(s2, dx2, dy2);
            ADD2(s2, s2, dz2);
            float lo, hi; UNPACK2(lo, hi, s2);
            dd[2 * j]     = fminf(dd[2 * j], lo);
            dd[2 * j + 1] = fminf(dd[2 * j + 1], hi);
        }

        // ---- thread argmax: fmax tree + equality bitmask (lowest i wins) ----
        float t16[16];
#pragma unroll
        for (int i = 0; i < 16; i++) t16[i] = fmaxf(dd[i], dd[i + 16]);
        float t8[8];
#pragma unroll
        for (int i = 0; i < 8; i++) t8[i] = fmaxf(t16[i], t16[i + 8]);
        float t4a = fmaxf(t8[0], t8[4]), t4b = fmaxf(t8[1], t8[5]);
        float t4c = fmaxf(t8[2], t8[6]), t4d = fmaxf(t8[3], t8[7]);
        float bv = fmaxf(fmaxf(t4a, t4b), fmaxf(t4c, t4d));
        unsigned m = 0;
#pragma unroll
        for (int i = 0; i < PPT; i++) m |= (dd[i] == bv) ? (1u << i) : 0u;
        int bi = __ffs(m) - 1;
        unsigned bpid = (unsigned)(pid0 + bi * FPS_THREADS);

        // ---- warp argmax via REDUX (tie -> smaller pid) ----
        unsigned vb   = __float_as_uint(bv);
        unsigned vmax = redux_max_u32(vb);
        unsigned pidw = redux_min_u32((vb == vmax) ? bpid : 0xffffffffu);

        const int bb = s & 1;
        const unsigned ph = (unsigned)((s >> 1) & 1);
        const unsigned lslot = bb ? lslot1 : lslot0;
        const unsigned lbar  = bb ? lbar1  : lbar0;

        // ---- lanes 0..7: publish warp winner to all 8 CTAs (fused tx) ----
        if (lane < CLUSTER) {
            unsigned long long key = ((unsigned long long)vmax << 32) | pidw;
            unsigned rslot = mapa_u32(lslot, (unsigned)lane);
            unsigned rbar  = mapa_u32(lbar, (unsigned)lane);
            ST_ASYNC_U64(rslot, key, rbar);
        }

        // ---- every warp: wait for all 32 candidates, reduce (1 slot/lane) ----
        MBAR_WAIT_PARITY_ACQ_CLUSTER(lbar, ph);

        // re-arm for iteration s+2 (warp0 lane0); safe: any s+2 store is
        // causally after our s+1 publish, which is program-ordered after this.
        if (tid == 0)
            MBAR_EXPECT_TX(lbar, 8u * NSLOT);

        unsigned long long ck = cslot[bb][lane];
        unsigned cv  = (unsigned)(ck >> 32);
        unsigned cp  = (unsigned)ck;
        unsigned cvm = redux_max_u32(cv);
        unsigned cpm = redux_min_u32((cv == cvm) ? cp : 0xffffffffu);

        // winner coords from global (uniform address -> broadcast load)
        float4 w = xb[cpm];
        cx = w.x; cy = w.y; cz = w.z;
    }

    CLUSTER_SYNC_ASM();
}

// ---------------------------------------------------------------------------
// Kernel 2: ball query + group — packed f32x2 main loop (proven R5/R6 version).
// ---------------------------------------------------------------------------
__global__ void __launch_bounds__(BQ_THREADS, 1)
ball_kernel(const float* __restrict__ cent, float* __restrict__ outc) {
    const int b  = blockIdx.x >> 4;
    const int s0 = (blockIdx.x & 15) * CPT;
    const int tid = threadIdx.x;
    const int lane = tid & 31, wid = tid >> 5;

    __shared__ float4 sc[CPT];
    __shared__ int cnt[CPT];
    __shared__ unsigned long long keys[CPT][CAP];
    __shared__ int sel[CPT][GRP];

    if (tid < CPT) {
        cnt[tid] = 0;
        const float* c = cent + (size_t)(b * SPTS + s0 + tid) * 3;
        sc[tid] = make_float4(c[0], c[1], c[2], 0.f);
    }
    __syncthreads();

    unsigned long long ncx2[CPT / 2], ncy2[CPT / 2], ncz2[CPT / 2];
#pragma unroll
    for (int j = 0; j < CPT / 2; j++) {
        float4 a = sc[2 * j], c = sc[2 * j + 1];
        PACK2(ncx2[j], negf(a.x), negf(c.x));
        PACK2(ncy2[j], negf(a.y), negf(c.y));
        PACK2(ncz2[j], negf(a.z), negf(c.z));
    }

    const float4* __restrict__ xb = g_xyz4 + b * NPTS;

    for (int pid = tid; pid < NPTS; pid += BQ_THREADS) {
        float4 p = xb[pid];
        unsigned long long px2, py2, pz2;
        PACK2(px2, p.x, p.x); PACK2(py2, p.y, p.y); PACK2(pz2, p.z, p.z);
#pragma unroll
        for (int j = 0; j < CPT / 2; j++) {
            unsigned long long dx2, dy2, dz2, s2;
            ADD2(dx2, px2, ncx2[j]);
            ADD2(dy2, py2, ncy2[j]);
            ADD2(dz2, pz2, ncz2[j]);
            MUL2(dx2, dx2, dx2);
            MUL2(dy2, dy2, dy2);
            MUL2(dz2, dz2, dz2);
            ADD2(s2, dx2, dy2);
            ADD2(s2, s2, dz2);
            float lo, hi; UNPACK2(lo, hi, s2);
            if (lo <= R2F) {
                int pos = atomicAdd(&cnt[2 * j], 1);
                if (pos < CAP)
                    keys[2 * j][pos] = ((unsigned long long)__float_as_uint(lo) << 32) | (unsigned)pid;
            }
            if (hi <= R2F) {
                int pos = atomicAdd(&cnt[2 * j + 1], 1);
                if (pos < CAP)
                    keys[2 * j + 1][pos] = ((unsigned long long)__float_as_uint(hi) << 32) | (unsigned)pid;
            }
        }
    }
    __syncthreads();

    for (int k = 0; k < CPT / 8; k++) {
        const int c = wid * (CPT / 8) + k;
        const int m = min(cnt[c], CAP);
        const int K = min(m, GRP);

        unsigned long long kk[CAP / 32];
#pragma unroll
        for (int j = 0; j < CAP / 32; j++) {
            int pos = lane + 32 * j;
            kk[j] = (pos < m) ? keys[c][pos] : 0xFFFFFFFFFFFFFFFFull;
        }
        for (int t = 0; t < K; t++) {
            unsigned long long lm = kk[0];
#pragma unroll
            for (int j = 1; j < CAP / 32; j++) lm = (kk[j] < lm) ? kk[j] : lm;
#pragma unroll
            for (int off = 16; off; off >>= 1) {
                unsigned long long o = __shfl_xor_sync(0xffffffffu, lm, off);
                lm = (o < lm) ? o : lm;
            }
#pragma unroll
            for (int j = 0; j < CAP / 32; j++) if (kk[j] == lm) kk[j] = 0xFFFFFFFFFFFFFFFFull;
            if (lane == 0) sel[c][t] = (int)(unsigned)(lm & 0xFFFFFFFFull);
        }

        float ccx, ccy, ccz;
        { float4 t4 = sc[c]; ccx = t4.x; ccy = t4.y; ccz = t4.z; }
        int need = GRP - K;
        int base = 0;
        while (need > 0) {
            int id = base + lane;
            bool oor = false;
            if (id < NPTS) {
                float4 p = xb[id];
                float dx = p.x - ccx, dy = p.y - ccy, dz = p.z - ccz;
                float sq = __fadd_rn(__fadd_rn(__fmul_rn(dx, dx), __fmul_rn(dy, dy)),
                                     __fmul_rn(dz, dz));
                oor = (sq > R2F);
            }
            unsigned msk = __ballot_sync(0xffffffffu, oor);
            int r = __popc(msk & ((1u << lane) - 1u));
            if (oor && r < need) sel[c][GRP - need + r] = id;
            int take = min(__popc(msk), need);
            need -= take;
            base += 32;
        }
    }
    __syncthreads();

    for (int k = 0; k < CPT / 8; k++) {
        const int c = wid * (CPT / 8) + k;
        const int s = s0 + c;
        float4 cc = sc[c];
        float* ob = outc + (size_t)((b * SPTS + s) * (GRP + 1)) * 3;
        if (lane == 0) { ob[0] = cc.x; ob[1] = cc.y; ob[2] = cc.z; }
        int idx = sel[c][lane];
        float4 p = xb[idx];
        float* og = ob + (size_t)(1 + lane) * 3;
        og[0] = p.x - cc.x; og[1] = p.y - cc.y; og[2] = p.z - cc.z;
    }
}

// ---------------------------------------------------------------------------
extern "C" void kernel_launch(void* const* d_in, const int* in_sizes, int n_in,
                              void* d_out, int out_size) {
    const float* xyz   = (const float*)d_in[0];
    const int*   finit = (const int*)d_in[1];
    float* out  = (float*)d_out;
    float* comb = out;                 // [B,S,33,3]
    float* cent = out + COMB_ELEMS;    // [B,S,3]

    pad_kernel<<<(BATCH * NPTS + 255) / 256, 256>>>(xyz);
    fps_kernel<<<BATCH * CLUSTER, FPS_THREADS>>>(finit, cent);
    ball_kernel<<<BATCH * (SPTS / CPT), BQ_THREADS>>>(cent, comb);
}

// round 13
// speedup vs baseline: 1.2314x; 1.0412x over previous
#include <cuda_runtime.h>
#include <cstdint>

#define BATCH 8
#define NPTS  32768
#define SPTS  512
#define GRP   32
#define BIGF  1e10f
#define R2F   0.04f

#define CLUSTER      8
#define FPS_THREADS  128
#define FPS_NWARP    (FPS_THREADS / 32)      // 4
#define NSLOT        (CLUSTER * FPS_NWARP)   // 32
#define PTS_BLK      (NPTS / CLUSTER)        // 4096
#define PPT          (PTS_BLK / FPS_THREADS) // 32
#define NP2          (PPT / 2)               // 16 packed slots

#define CPT        32
#define BQ_THREADS 256
#define CAP        128

#define COMB_ELEMS (BATCH * SPTS * (GRP + 1) * 3)  // 405504

__device__ float4 g_xyz4[BATCH * NPTS];

// ---------------------------------------------------------------------------
// helpers
// ---------------------------------------------------------------------------
__device__ __forceinline__ unsigned smem_u32(const void* p) {
    unsigned a;
    asm("{ .reg .u64 t; cvta.to.shared.u64 t, %1; cvt.u32.u64 %0, t; }" : "=r"(a) : "l"(p));
    return a;
}
__device__ __forceinline__ unsigned redux_max_u32(unsigned v) {
    unsigned r; asm("redux.sync.max.u32 %0, %1, 0xffffffff;" : "=r"(r) : "r"(v)); return r;
}
__device__ __forceinline__ unsigned redux_min_u32(unsigned v) {
    unsigned r; asm("redux.sync.min.u32 %0, %1, 0xffffffff;" : "=r"(r) : "r"(v)); return r;
}
__device__ __forceinline__ unsigned mapa_u32(unsigned laddr, unsigned rank) {
    unsigned r; asm("mapa.shared::cluster.u32 %0, %1, %2;" : "=r"(r) : "r"(laddr), "r"(rank));
    return r;
}

// packed f32x2 (Blackwell): IEEE rn per component — bit-identical to scalar rn
#define PACK2(d, lo, hi)  asm("mov.b64 %0, {%1, %2};" : "=l"(d) : "f"(lo), "f"(hi))
#define UNPACK2(lo, hi, s) asm("mov.b64 {%0, %1}, %2;" : "=f"(lo), "=f"(hi) : "l"(s))
#define ADD2(d, a, b) asm("add.rn.f32x2 %0, %1, %2;" : "=l"(d) : "l"(a), "l"(b))
#define MUL2(d, a, b) asm("mul.rn.f32x2 %0, %1, %2;" : "=l"(d) : "l"(a), "l"(b))

__device__ __forceinline__ float negf(float a) {
    return __uint_as_float(__float_as_uint(a) ^ 0x80000000u);
}

#define MBAR_INIT(addr, cnt) \
    asm volatile("mbarrier.init.shared.b64 [%0], %1;" :: "r"(addr), "r"(cnt) : "memory")

#define MBAR_EXPECT_TX(addr, bytes) \
    asm volatile("mbarrier.arrive.expect_tx.shared.b64 _, [%0], %1;" \
                 :: "r"(addr), "r"(bytes) : "memory")

// fused data + barrier-signal store to a peer CTA's smem (single fabric hop)
#define ST_ASYNC_U64(rslot, val, rbar) \
    asm volatile("st.async.shared::cluster.mbarrier::complete_tx::bytes.b64 [%0], %1, [%2];" \
                 :: "r"(rslot), "l"(val), "r"(rbar) : "memory")

#define MBAR_WAIT_PARITY_ACQ_CLUSTER(mbar, parity) do {                            \
    unsigned _m = (mbar), _p = (parity), _d;                                       \
    asm volatile("{\n\t.reg .pred p;\n\t"                                          \
        "mbarrier.try_wait.parity.acquire.cluster.shared::cta.b64 p, [%1], %2;\n\t"\
        "selp.b32 %0, 1, 0, p;\n\t}"                                               \
        : "=r"(_d) : "r"(_m), "r"(_p) : "memory");                                 \
    if (!_d) {                                                                     \
        asm volatile("{\n\t.reg .pred P1;\n"                                       \
            "WL_%=:\n\t"                                                           \
            "mbarrier.try_wait.parity.acquire.cluster.shared::cta.b64 P1, [%0], %1;\n\t" \
            "@P1 bra.uni WD_%=;\n\t"                                               \
            "bra.uni WL_%=;\n"                                                     \
            "WD_%=:\n\t}" :: "r"(_m), "r"(_p) : "memory");                         \
    }                                                                              \
} while (0)

#define CLUSTER_SYNC_ASM() do {                                        \
    asm volatile("barrier.cluster.arrive.aligned;" ::: "memory");      \
    asm volatile("barrier.cluster.wait.aligned;" ::: "memory");        \
} while (0)

// ---------------------------------------------------------------------------
// Kernel 0: pack xyz [B,N,3] -> float4
// ---------------------------------------------------------------------------
__global__ void pad_kernel(const float* __restrict__ xyz) {
    int i = blockIdx.x * blockDim.x + threadIdx.x;
    if (i < BATCH * NPTS) {
        g_xyz4[i] = make_float4(xyz[3 * i], xyz[3 * i + 1], xyz[3 * i + 2], 0.f);
    }
}

// ---------------------------------------------------------------------------
// Kernel 1: FPS — flat st.async exchange (R12, proven) with:
//  - incremental running max inside the distance loop (ALU pipe, frees tail)
//  - hoisted mapa remote addresses
// ---------------------------------------------------------------------------
__global__ void __cluster_dims__(CLUSTER, 1, 1) __launch_bounds__(FPS_THREADS, 1)
fps_kernel(const int* __restrict__ finit, float* __restrict__ out_cent) {
    const int tid  = threadIdx.x;
    const int lane = tid & 31, wid = tid >> 5;
    unsigned rank;
    asm("mov.u32 %0, %%cluster_ctarank;" : "=r"(rank));
    const int b = blockIdx.x / CLUSTER;
    const float4* __restrict__ xb = g_xyz4 + b * NPTS;

    __shared__ unsigned long long cslot[2][NSLOT];   // 32 warp winners (dbl buf)
    __shared__ unsigned long long bars[2];

    if (tid == 0) {
        MBAR_INIT(smem_u32(&bars[0]), 1);
        MBAR_INIT(smem_u32(&bars[1]), 1);
        MBAR_EXPECT_TX(smem_u32(&bars[0]), 8u * NSLOT);
        MBAR_EXPECT_TX(smem_u32(&bars[1]), 8u * NSLOT);
    }
    __syncthreads();
    CLUSTER_SYNC_ASM();   // init+arm visible cluster-wide before any st.async

    // register-resident points, packed pairs: slot j = points (2j, 2j+1),
    // point i lives at pid0 + i*FPS_THREADS
    unsigned long long pxx[NP2], pyy[NP2], pzz[NP2];
    float dd[PPT];
    const int pid0 = rank * PTS_BLK + tid;
#pragma unroll
    for (int j = 0; j < NP2; j++) {
        float4 a = xb[pid0 + (2 * j) * FPS_THREADS];
        float4 c = xb[pid0 + (2 * j + 1) * FPS_THREADS];
        PACK2(pxx[j], a.x, c.x);
        PACK2(pyy[j], a.y, c.y);
        PACK2(pzz[j], a.z, c.z);
        dd[2 * j] = BIGF; dd[2 * j + 1] = BIGF;
    }

    // hoisted remote addresses: lane r (<8) targets rank r, slot rank*4+wid
    const unsigned lslot0 = smem_u32(&cslot[0][rank * FPS_NWARP + wid]);
    const unsigned lslot1 = smem_u32(&cslot[1][rank * FPS_NWARP + wid]);
    const unsigned lbar0  = smem_u32(&bars[0]);
    const unsigned lbar1  = smem_u32(&bars[1]);
    const unsigned tr     = (unsigned)(lane & 7);
    const unsigned rslot0 = mapa_u32(lslot0, tr);
    const unsigned rslot1 = mapa_u32(lslot1, tr);
    const unsigned rbar0  = mapa_u32(lbar0, tr);
    const unsigned rbar1  = mapa_u32(lbar1, tr);

    float4 c0 = xb[finit[b]];
    float cx = c0.x, cy = c0.y, cz = c0.z;

    for (int s = 0; s < SPTS; s++) {
        if (rank == 0 && tid == 0) {
            float* o = out_cent + (size_t)(b * SPTS + s) * 3;
            o[0] = cx; o[1] = cy; o[2] = cz;
        }
        if (s == SPTS - 1) break;

        // ---- packed distance update: (p - c)^2 as p + (-c), exact rn ----
        // running max rides the ALU pipe under the fma-pipe issue floor
        unsigned long long ncx2, ncy2, ncz2;
        {
            float nx = negf(cx), ny = negf(cy), nz = negf(cz);
            PACK2(ncx2, nx, nx); PACK2(ncy2, ny, ny); PACK2(ncz2, nz, nz);
        }
        float bv = -1.f;
#pragma unroll
        for (int j = 0; j < NP2; j++) {
            unsigned long long dx2, dy2, dz2, s2;
            ADD2(dx2, pxx[j], ncx2);
            ADD2(dy2, pyy[j], ncy2);
            ADD2(dz2, pzz[j], ncz2);
            MUL2(dx2, dx2, dx2);
            MUL2(dy2, dy2, dy2);
            MUL2(dz2, dz2, dz2);
            ADD2(s2, dx2, dy2);
            ADD2(s2, s2, dz2);
            float lo, hi; UNPACK2(lo, hi, s2);
            float n0 = fminf(dd[2 * j], lo);
            float n1 = fminf(dd[2 * j + 1], hi);
            dd[2 * j] = n0; dd[2 * j + 1] = n1;
            bv = fmaxf(bv, n0);
            bv = fmaxf(bv, n1);
        }

        // ---- thread argmax index: equality bitmask (lowest i wins) ----
        unsigned m = 0;
#pragma unroll
        for (int i = 0; i < PPT; i++) m |= (dd[i] == bv) ? (1u << i) : 0u;
        int bi = __ffs(m) - 1;
        unsigned bpid = (unsigned)(pid0 + bi * FPS_THREADS);

        // ---- warp argmax via REDUX (tie -> smaller pid) ----
        unsigned vb   = __float_as_uint(bv);
        unsigned vmax = redux_max_u32(vb);
        unsigned pidw = redux_min_u32((vb == vmax) ? bpid : 0xffffffffu);

        const int bb = s & 1;
        const unsigned ph = (unsigned)((s >> 1) & 1);

        // ---- lanes 0..7: publish warp winner to all 8 CTAs (fused tx) ----
        if (lane < CLUSTER) {
            unsigned long long key = ((unsigned long long)vmax << 32) | pidw;
            ST_ASYNC_U64(bb ? rslot1 : rslot0, key, bb ? rbar1 : rbar0);
        }

        // ---- every warp: wait for all 32 candidates, reduce (1 slot/lane) ----
        const unsigned lbar = bb ? lbar1 : lbar0;
        MBAR_WAIT_PARITY_ACQ_CLUSTER(lbar, ph);

        // re-arm for iteration s+2 (warp0 lane0); safe: any s+2 store is
        // causally after our s+1 publish, which is program-ordered after this.
        if (tid == 0)
            MBAR_EXPECT_TX(lbar, 8u * NSLOT);

        unsigned long long ck = cslot[bb][lane];
        unsigned cv  = (unsigned)(ck >> 32);
        unsigned cp  = (unsigned)ck;
        unsigned cvm = redux_max_u32(cv);
        unsigned cpm = redux_min_u32((cv == cvm) ? cp : 0xffffffffu);

        // winner coords from global (uniform address -> broadcast load)
        float4 w = xb[cpm];
        cx = w.x; cy = w.y; cz = w.z;
    }

    CLUSTER_SYNC_ASM();
}

// ---------------------------------------------------------------------------
// Kernel 2: ball query + group — packed f32x2 main loop (proven). Selection
// now uses split redux_min (dist bits, then pid) instead of a u64 shfl tree.
// ---------------------------------------------------------------------------
__global__ void __launch_bounds__(BQ_THREADS, 1)
ball_kernel(const float* __restrict__ cent, float* __restrict__ outc) {
    const int b  = blockIdx.x >> 4;
    const int s0 = (blockIdx.x & 15) * CPT;
    const int tid = threadIdx.x;
    const int lane = tid & 31, wid = tid >> 5;

    __shared__ float4 sc[CPT];
    __shared__ int cnt[CPT];
    __shared__ unsigned long long keys[CPT][CAP];
    __shared__ int sel[CPT][GRP];

    if (tid < CPT) {
        cnt[tid] = 0;
        const float* c = cent + (size_t)(b * SPTS + s0 + tid) * 3;
        sc[tid] = make_float4(c[0], c[1], c[2], 0.f);
    }
    __syncthreads();

    unsigned long long ncx2[CPT / 2], ncy2[CPT / 2], ncz2[CPT / 2];
#pragma unroll
    for (int j = 0; j < CPT / 2; j++) {
        float4 a = sc[2 * j], c = sc[2 * j + 1];
        PACK2(ncx2[j], negf(a.x), negf(c.x));
        PACK2(ncy2[j], negf(a.y), negf(c.y));
        PACK2(ncz2[j], negf(a.z), negf(c.z));
    }

    const float4* __restrict__ xb = g_xyz4 + b * NPTS;

    for (int pid = tid; pid < NPTS; pid += BQ_THREADS) {
        float4 p = xb[pid];
        unsigned long long px2, py2, pz2;
        PACK2(px2, p.x, p.x); PACK2(py2, p.y, p.y); PACK2(pz2, p.z, p.z);
#pragma unroll
        for (int j = 0; j < CPT / 2; j++) {
            unsigned long long dx2, dy2, dz2, s2;
            ADD2(dx2, px2, ncx2[j]);
            ADD2(dy2, py2, ncy2[j]);
            ADD2(dz2, pz2, ncz2[j]);
            MUL2(dx2, dx2, dx2);
            MUL2(dy2, dy2, dy2);
            MUL2(dz2, dz2, dz2);
            ADD2(s2, dx2, dy2);
            ADD2(s2, s2, dz2);
            float lo, hi; UNPACK2(lo, hi, s2);
            if (lo <= R2F) {
                int pos = atomicAdd(&cnt[2 * j], 1);
                if (pos < CAP)
                    keys[2 * j][pos] = ((unsigned long long)__float_as_uint(lo) << 32) | (unsigned)pid;
            }
            if (hi <= R2F) {
                int pos = atomicAdd(&cnt[2 * j + 1], 1);
                if (pos < CAP)
                    keys[2 * j + 1][pos] = ((unsigned long long)__float_as_uint(hi) << 32) | (unsigned)pid;
            }
        }
    }
    __syncthreads();

    for (int k = 0; k < CPT / 8; k++) {
        const int c = wid * (CPT / 8) + k;
        const int m = min(cnt[c], CAP);
        const int K = min(m, GRP);

        unsigned long long kk[CAP / 32];
#pragma unroll
        for (int j = 0; j < CAP / 32; j++) {
            int pos = lane + 32 * j;
            kk[j] = (pos < m) ? keys[c][pos] : 0xFFFFFFFFFFFFFFFFull;
        }
        for (int t = 0; t < K; t++) {
            unsigned long long lmin = kk[0];
#pragma unroll
            for (int j = 1; j < CAP / 32; j++) lmin = (kk[j] < lmin) ? kk[j] : lmin;
            unsigned ld = (unsigned)(lmin >> 32);
            unsigned lp = (unsigned)lmin;
            unsigned dmin = redux_min_u32(ld);
            unsigned pidm = redux_min_u32((ld == dmin) ? lp : 0xffffffffu);
            unsigned long long lm = ((unsigned long long)dmin << 32) | pidm;
#pragma unroll
            for (int j = 0; j < CAP / 32; j++) if (kk[j] == lm) kk[j] = 0xFFFFFFFFFFFFFFFFull;
            if (lane == 0) sel[c][t] = (int)pidm;
        }

        float ccx, ccy, ccz;
        { float4 t4 = sc[c]; ccx = t4.x; ccy = t4.y; ccz = t4.z; }
        int need = GRP - K;
        int base = 0;
        while (need > 0) {
            int id = base + lane;
            bool oor = false;
            if (id < NPTS) {
                float4 p = xb[id];
                float dx = p.x - ccx, dy = p.y - ccy, dz = p.z - ccz;
                float sq = __fadd_rn(__fadd_rn(__fmul_rn(dx, dx), __fmul_rn(dy, dy)),
                                     __fmul_rn(dz, dz));
                oor = (sq > R2F);
            }
            unsigned msk = __ballot_sync(0xffffffffu, oor);
            int r = __popc(msk & ((1u << lane) - 1u));
            if (oor && r < need) sel[c][GRP - need + r] = id;
            int take = min(__popc(msk), need);
            need -= take;
            base += 32;
        }
    }
    __syncthreads();

    for (int k = 0; k < CPT / 8; k++) {
        const int c = wid * (CPT / 8) + k;
        const int s = s0 + c;
        float4 cc = sc[c];
        float* ob = outc + (size_t)((b * SPTS + s) * (GRP + 1)) * 3;
        if (lane == 0) { ob[0] = cc.x; ob[1] = cc.y; ob[2] = cc.z; }
        int idx = sel[c][lane];
        float4 p = xb[idx];
        float* og = ob + (size_t)(1 + lane) * 3;
        og[0] = p.x - cc.x; og[1] = p.y - cc.y; og[2] = p.z - cc.z;
    }
}

// ---------------------------------------------------------------------------
extern "C" void kernel_launch(void* const* d_in, const int* in_sizes, int n_in,
                              void* d_out, int out_size) {
    const float* xyz   = (const float*)d_in[0];
    const int*   finit = (const int*)d_in[1];
    float* out  = (float*)d_out;
    float* comb = out;                 // [B,S,33,3]
    float* cent = out + COMB_ELEMS;    // [B,S,3]

    pad_kernel<<<(BATCH * NPTS + 255) / 256, 256>>>(xyz);
    fps_kernel<<<BATCH * CLUSTER, FPS_THREADS>>>(finit, cent);
    ball_kernel<<<BATCH * (SPTS / CPT), BQ_THREADS>>>(cent, comb);
}

// round 14
// speedup vs baseline: 1.2562x; 1.0201x over previous
#include <cuda_runtime.h>
#include <cstdint>

#define BATCH 8
#define NPTS  32768
#define SPTS  512
#define GRP   32
#define BIGF  1e10f
#define R2F   0.04f

#define CLUSTER      8
#define FPS_THREADS  128
#define FPS_NWARP    (FPS_THREADS / 32)      // 4
#define NSLOT        (CLUSTER * FPS_NWARP)   // 32
#define PTS_BLK      (NPTS / CLUSTER)        // 4096
#define PPT          (PTS_BLK / FPS_THREADS) // 32
#define NP2          (PPT / 2)               // 16 packed slots

#define CPT        32
#define BQ_THREADS 256
#define CAP        128

#define COMB_ELEMS (BATCH * SPTS * (GRP + 1) * 3)  // 405504
#define FPS_DSMEM  (PTS_BLK * 16)                  // 64KB staging

__device__ float4 g_xyz4[BATCH * NPTS];

// ---------------------------------------------------------------------------
// helpers
// ---------------------------------------------------------------------------
__device__ __forceinline__ unsigned smem_u32(const void* p) {
    unsigned a;
    asm("{ .reg .u64 t; cvta.to.shared.u64 t, %1; cvt.u32.u64 %0, t; }" : "=r"(a) : "l"(p));
    return a;
}
__device__ __forceinline__ unsigned redux_max_u32(unsigned v) {
    unsigned r; asm("redux.sync.max.u32 %0, %1, 0xffffffff;" : "=r"(r) : "r"(v)); return r;
}
__device__ __forceinline__ unsigned redux_min_u32(unsigned v) {
    unsigned r; asm("redux.sync.min.u32 %0, %1, 0xffffffff;" : "=r"(r) : "r"(v)); return r;
}
__device__ __forceinline__ unsigned mapa_u32(unsigned laddr, unsigned rank) {
    unsigned r; asm("mapa.shared::cluster.u32 %0, %1, %2;" : "=r"(r) : "r"(laddr), "r"(rank));
    return r;
}

// packed f32x2 (Blackwell): IEEE rn per component — bit-identical to scalar rn
#define PACK2(d, lo, hi)  asm("mov.b64 %0, {%1, %2};" : "=l"(d) : "f"(lo), "f"(hi))
#define UNPACK2(lo, hi, s) asm("mov.b64 {%0, %1}, %2;" : "=f"(lo), "=f"(hi) : "l"(s))
#define ADD2(d, a, b) asm("add.rn.f32x2 %0, %1, %2;" : "=l"(d) : "l"(a), "l"(b))
#define MUL2(d, a, b) asm("mul.rn.f32x2 %0, %1, %2;" : "=l"(d) : "l"(a), "l"(b))

__device__ __forceinline__ float negf(float a) {
    return __uint_as_float(__float_as_uint(a) ^ 0x80000000u);
}

#define MBAR_INIT(addr, cnt) \
    asm volatile("mbarrier.init.shared.b64 [%0], %1;" :: "r"(addr), "r"(cnt) : "memory")

#define MBAR_EXPECT_TX(addr, bytes) \
    asm volatile("mbarrier.arrive.expect_tx.shared.b64 _, [%0], %1;" \
                 :: "r"(addr), "r"(bytes) : "memory")

// fused data + barrier-signal store to a peer CTA's smem (single fabric hop)
#define ST_ASYNC_U64(rslot, val, rbar) \
    asm volatile("st.async.shared::cluster.mbarrier::complete_tx::bytes.b64 [%0], %1, [%2];" \
                 :: "r"(rslot), "l"(val), "r"(rbar) : "memory")

#define MBAR_WAIT_PARITY_ACQ_CLUSTER(mbar, parity) do {                            \
    unsigned _m = (mbar), _p = (parity), _d;                                       \
    asm volatile("{\n\t.reg .pred p;\n\t"                                          \
        "mbarrier.try_wait.parity.acquire.cluster.shared::cta.b64 p, [%1], %2;\n\t"\
        "selp.b32 %0, 1, 0, p;\n\t}"                                               \
        : "=r"(_d) : "r"(_m), "r"(_p) : "memory");                                 \
    if (!_d) {                                                                     \
        asm volatile("{\n\t.reg .pred P1;\n"                                       \
            "WL_%=:\n\t"                                                           \
            "mbarrier.try_wait.parity.acquire.cluster.shared::cta.b64 P1, [%0], %1;\n\t" \
            "@P1 bra.uni WD_%=;\n\t"                                               \
            "bra.uni WL_%=;\n"                                                     \
            "WD_%=:\n\t}" :: "r"(_m), "r"(_p) : "memory");                         \
    }                                                                              \
} while (0)

#define CLUSTER_SYNC_ASM() do {                                        \
    asm volatile("barrier.cluster.arrive.aligned;" ::: "memory");      \
    asm volatile("barrier.cluster.wait.aligned;" ::: "memory");        \
} while (0)

// ---------------------------------------------------------------------------
// Kernel 0: pack xyz [B,N,3] -> float4
// ---------------------------------------------------------------------------
__global__ void pad_kernel(const float* __restrict__ xyz) {
    int i = blockIdx.x * blockDim.x + threadIdx.x;
    if (i < BATCH * NPTS) {
        g_xyz4[i] = make_float4(xyz[3 * i], xyz[3 * i + 1], xyz[3 * i + 2], 0.f);
    }
}

// ---------------------------------------------------------------------------
// Kernel 1: FPS — R13 structure (flat st.async exchange, running max) with
// DSMEM point staging: each CTA keeps its 4096-point partition in 64KB smem;
// the winner-coord read becomes a uniform ld.shared::cluster from the owner
// CTA (~215 cyc cross / 38 local) instead of an L2 LDG.
// ---------------------------------------------------------------------------
__global__ void __cluster_dims__(CLUSTER, 1, 1) __launch_bounds__(FPS_THREADS, 1)
fps_kernel(const int* __restrict__ finit, float* __restrict__ out_cent) {
    extern __shared__ float4 stage[];     // [PTS_BLK] this CTA's points
    const int tid  = threadIdx.x;
    const int lane = tid & 31, wid = tid >> 5;
    unsigned rank;
    asm("mov.u32 %0, %%cluster_ctarank;" : "=r"(rank));
    const int b = blockIdx.x / CLUSTER;
    const float4* __restrict__ xb = g_xyz4 + b * NPTS;

    __shared__ unsigned long long cslot[2][NSLOT];   // 32 warp winners (dbl buf)
    __shared__ unsigned long long bars[2];

    if (tid == 0) {
        MBAR_INIT(smem_u32(&bars[0]), 1);
        MBAR_INIT(smem_u32(&bars[1]), 1);
        MBAR_EXPECT_TX(smem_u32(&bars[0]), 8u * NSLOT);
        MBAR_EXPECT_TX(smem_u32(&bars[1]), 8u * NSLOT);
    }

    // stage this CTA's partition into smem (read by peers via DSMEM)
    const int pbase = rank * PTS_BLK;
    for (int i = tid; i < PTS_BLK; i += FPS_THREADS)
        stage[i] = xb[pbase + i];

    __syncthreads();
    CLUSTER_SYNC_ASM();   // barriers + staging visible cluster-wide

    // register-resident points, packed pairs: slot j = points (2j, 2j+1),
    // point i lives at pid0 + i*FPS_THREADS
    unsigned long long pxx[NP2], pyy[NP2], pzz[NP2];
    float dd[PPT];
    const int pid0 = pbase + tid;
#pragma unroll
    for (int j = 0; j < NP2; j++) {
        float4 a = stage[tid + (2 * j) * FPS_THREADS];
        float4 c = stage[tid + (2 * j + 1) * FPS_THREADS];
        PACK2(pxx[j], a.x, c.x);
        PACK2(pyy[j], a.y, c.y);
        PACK2(pzz[j], a.z, c.z);
        dd[2 * j] = BIGF; dd[2 * j + 1] = BIGF;
    }

    // hoisted remote addresses: lane r (<8) targets rank r, slot rank*4+wid
    const unsigned lslot0 = smem_u32(&cslot[0][rank * FPS_NWARP + wid]);
    const unsigned lslot1 = smem_u32(&cslot[1][rank * FPS_NWARP + wid]);
    const unsigned lbar0  = smem_u32(&bars[0]);
    const unsigned lbar1  = smem_u32(&bars[1]);
    const unsigned tr     = (unsigned)(lane & 7);
    const unsigned rslot0 = mapa_u32(lslot0, tr);
    const unsigned rslot1 = mapa_u32(lslot1, tr);
    const unsigned rbar0  = mapa_u32(lbar0, tr);
    const unsigned rbar1  = mapa_u32(lbar1, tr);
    const unsigned stage_base = smem_u32(&stage[0]);

    float4 c0 = xb[finit[b]];
    float cx = c0.x, cy = c0.y, cz = c0.z;

    for (int s = 0; s < SPTS; s++) {
        if (rank == 0 && tid == 0) {
            float* o = out_cent + (size_t)(b * SPTS + s) * 3;
            o[0] = cx; o[1] = cy; o[2] = cz;
        }
        if (s == SPTS - 1) break;

        // ---- packed distance update: (p - c)^2 as p + (-c), exact rn ----
        unsigned long long ncx2, ncy2, ncz2;
        {
            float nx = negf(cx), ny = negf(cy), nz = negf(cz);
            PACK2(ncx2, nx, nx); PACK2(ncy2, ny, ny); PACK2(ncz2, nz, nz);
        }
        float bv = -1.f;
#pragma unroll
        for (int j = 0; j < NP2; j++) {
            unsigned long long dx2, dy2, dz2, s2;
            ADD2(dx2, pxx[j], ncx2);
            ADD2(dy2, pyy[j], ncy2);
            ADD2(dz2, pzz[j], ncz2);
            MUL2(dx2, dx2, dx2);
            MUL2(dy2, dy2, dy2);
            MUL2(dz2, dz2, dz2);
            ADD2(s2, dx2, dy2);
            ADD2(s2, s2, dz2);
            float lo, hi; UNPACK2(lo, hi, s2);
            float n0 = fminf(dd[2 * j], lo);
            float n1 = fminf(dd[2 * j + 1], hi);
            dd[2 * j] = n0; dd[2 * j + 1] = n1;
            bv = fmaxf(bv, n0);
            bv = fmaxf(bv, n1);
        }

        // ---- thread argmax index: equality bitmask (lowest i wins) ----
        unsigned m = 0;
#pragma unroll
        for (int i = 0; i < PPT; i++) m |= (dd[i] == bv) ? (1u << i) : 0u;
        int bi = __ffs(m) - 1;
        unsigned bpid = (unsigned)(pid0 + bi * FPS_THREADS);

        // ---- warp argmax via REDUX (tie -> smaller pid) ----
        unsigned vb   = __float_as_uint(bv);
        unsigned vmax = redux_max_u32(vb);
        unsigned pidw = redux_min_u32((vb == vmax) ? bpid : 0xffffffffu);

        const int bb = s & 1;
        const unsigned ph = (unsigned)((s >> 1) & 1);

        // ---- lanes 0..7: publish warp winner to all 8 CTAs (fused tx) ----
        if (lane < CLUSTER) {
            unsigned long long key = ((unsigned long long)vmax << 32) | pidw;
            ST_ASYNC_U64(bb ? rslot1 : rslot0, key, bb ? rbar1 : rbar0);
        }

        // ---- every warp: wait for all 32 candidates, reduce (1 slot/lane) ----
        const unsigned lbar = bb ? lbar1 : lbar0;
        MBAR_WAIT_PARITY_ACQ_CLUSTER(lbar, ph);

        // re-arm for iteration s+2 (warp0 lane0); safe: any s+2 store is
        // causally after our s+1 publish, which is program-ordered after this.
        if (tid == 0)
            MBAR_EXPECT_TX(lbar, 8u * NSLOT);

        unsigned long long ck = cslot[bb][lane];
        unsigned cv  = (unsigned)(ck >> 32);
        unsigned cp  = (unsigned)ck;
        unsigned cvm = redux_max_u32(cv);
        unsigned cpm = redux_min_u32((cv == cvm) ? cp : 0xffffffffu);

        // winner coords from the owner CTA's smem staging (uniform DSMEM read)
        {
            unsigned owner = cpm >> 12;            // / PTS_BLK
            unsigned off   = cpm & (PTS_BLK - 1);
            unsigned raddr = mapa_u32(stage_base + off * 16u, owner);
            unsigned long long wxy, wzw;
            asm volatile("ld.shared::cluster.v2.b64 {%0, %1}, [%2];"
                         : "=l"(wxy), "=l"(wzw) : "r"(raddr));
            cx = __uint_as_float((unsigned)wxy);
            cy = __uint_as_float((unsigned)(wxy >> 32));
            cz = __uint_as_float((unsigned)wzw);
        }
    }

    CLUSTER_SYNC_ASM();   // keep smem staging alive until all CTAs done
}

// ---------------------------------------------------------------------------
// Kernel 2: ball query + group — packed f32x2 main loop (proven R13 version).
// ---------------------------------------------------------------------------
__global__ void __launch_bounds__(BQ_THREADS, 1)
ball_kernel(const float* __restrict__ cent, float* __restrict__ outc) {
    const int b  = blockIdx.x >> 4;
    const int s0 = (blockIdx.x & 15) * CPT;
    const int tid = threadIdx.x;
    const int lane = tid & 31, wid = tid >> 5;

    __shared__ float4 sc[CPT];
    __shared__ int cnt[CPT];
    __shared__ unsigned long long keys[CPT][CAP];
    __shared__ int sel[CPT][GRP];

    if (tid < CPT) {
        cnt[tid] = 0;
        const float* c = cent + (size_t)(b * SPTS + s0 + tid) * 3;
        sc[tid] = make_float4(c[0], c[1], c[2], 0.f);
    }
    __syncthreads();

    unsigned long long ncx2[CPT / 2], ncy2[CPT / 2], ncz2[CPT / 2];
#pragma unroll
    for (int j = 0; j < CPT / 2; j++) {
        float4 a = sc[2 * j], c = sc[2 * j + 1];
        PACK2(ncx2[j], negf(a.x), negf(c.x));
        PACK2(ncy2[j], negf(a.y), negf(c.y));
        PACK2(ncz2[j], negf(a.z), negf(c.z));
    }

    const float4* __restrict__ xb = g_xyz4 + b * NPTS;

    for (int pid = tid; pid < NPTS; pid += BQ_THREADS) {
        float4 p = xb[pid];
        unsigned long long px2, py2, pz2;
        PACK2(px2, p.x, p.x); PACK2(py2, p.y, p.y); PACK2(pz2, p.z, p.z);
#pragma unroll
        for (int j = 0; j < CPT / 2; j++) {
            unsigned long long dx2, dy2, dz2, s2;
            ADD2(dx2, px2, ncx2[j]);
            ADD2(dy2, py2, ncy2[j]);
            ADD2(dz2, pz2, ncz2[j]);
            MUL2(dx2, dx2, dx2);
            MUL2(dy2, dy2, dy2);
            MUL2(dz2, dz2, dz2);
            ADD2(s2, dx2, dy2);
            ADD2(s2, s2, dz2);
            float lo, hi; UNPACK2(lo, hi, s2);
            if (lo <= R2F) {
                int pos = atomicAdd(&cnt[2 * j], 1);
                if (pos < CAP)
                    keys[2 * j][pos] = ((unsigned long long)__float_as_uint(lo) << 32) | (unsigned)pid;
            }
            if (hi <= R2F) {
                int pos = atomicAdd(&cnt[2 * j + 1], 1);
                if (pos < CAP)
                    keys[2 * j + 1][pos] = ((unsigned long long)__float_as_uint(hi) << 32) | (unsigned)pid;
            }
        }
    }
    __syncthreads();

    for (int k = 0; k < CPT / 8; k++) {
        const int c = wid * (CPT / 8) + k;
        const int m = min(cnt[c], CAP);
        const int K = min(m, GRP);

        unsigned long long kk[CAP / 32];
#pragma unroll
        for (int j = 0; j < CAP / 32; j++) {
            int pos = lane + 32 * j;
            kk[j] = (pos < m) ? keys[c][pos] : 0xFFFFFFFFFFFFFFFFull;
        }
        for (int t = 0; t < K; t++) {
            unsigned long long lmin = kk[0];
#pragma unroll
            for (int j = 1; j < CAP / 32; j++) lmin = (kk[j] < lmin) ? kk[j] : lmin;
            unsigned ld = (unsigned)(lmin >> 32);
            unsigned lp = (unsigned)lmin;
            unsigned dmin = redux_min_u32(ld);
            unsigned pidm = redux_min_u32((ld == dmin) ? lp : 0xffffffffu);
            unsigned long long lm = ((unsigned long long)dmin << 32) | pidm;
#pragma unroll
            for (int j = 0; j < CAP / 32; j++) if (kk[j] == lm) kk[j] = 0xFFFFFFFFFFFFFFFFull;
            if (lane == 0) sel[c][t] = (int)pidm;
        }

        float ccx, ccy, ccz;
        { float4 t4 = sc[c]; ccx = t4.x; ccy = t4.y; ccz = t4.z; }
        int need = GRP - K;
        int base = 0;
        while (need > 0) {
            int id = base + lane;
            bool oor = false;
            if (id < NPTS) {
                float4 p = xb[id];
                float dx = p.x - ccx, dy = p.y - ccy, dz = p.z - ccz;
                float sq = __fadd_rn(__fadd_rn(__fmul_rn(dx, dx), __fmul_rn(dy, dy)),
                                     __fmul_rn(dz, dz));
                oor = (sq > R2F);
            }
            unsigned msk = __ballot_sync(0xffffffffu, oor);
            int r = __popc(msk & ((1u << lane) - 1u));
            if (oor && r < need) sel[c][GRP - need + r] = id;
            int take = min(__popc(msk), need);
            need -= take;
            base += 32;
        }
    }
    __syncthreads();

    for (int k = 0; k < CPT / 8; k++) {
        const int c = wid * (CPT / 8) + k;
        const int s = s0 + c;
        float4 cc = sc[c];
        float* ob = outc + (size_t)((b * SPTS + s) * (GRP + 1)) * 3;
        if (lane == 0) { ob[0] = cc.x; ob[1] = cc.y; ob[2] = cc.z; }
        int idx = sel[c][lane];
        float4 p = xb[idx];
        float* og = ob + (size_t)(1 + lane) * 3;
        og[0] = p.x - cc.x; og[1] = p.y - cc.y; og[2] = p.z - cc.z;
    }
}

// ---------------------------------------------------------------------------
extern "C" void kernel_launch(void* const* d_in, const int* in_sizes, int n_in,
                              void* d_out, int out_size) {
    const float* xyz   = (const float*)d_in[0];
    const int*   finit = (const int*)d_in[1];
    float* out  = (float*)d_out;
    float* comb = out;                 // [B,S,33,3]
    float* cent = out + COMB_ELEMS;    // [B,S,3]

    // allow 64KB dynamic smem for the FPS staging (idempotent, not an alloc)
    cudaFuncSetAttribute(fps_kernel, cudaFuncAttributeMaxDynamicSharedMemorySize,
                         FPS_DSMEM);

    pad_kernel<<<(BATCH * NPTS + 255) / 256, 256>>>(xyz);
    fps_kernel<<<BATCH * CLUSTER, FPS_THREADS, FPS_DSMEM>>>(finit, cent);
    ball_kernel<<<BATCH * (SPTS / CPT), BQ_THREADS>>>(cent, comb);
}

// round 15
// speedup vs baseline: 1.2948x; 1.0307x over previous
#include <cuda_runtime.h>
#include <cstdint>

#define BATCH 8
#define NPTS  32768
#define SPTS  512
#define GRP   32
#define BIGF  1e10f
#define R2F   0.04f

#define CLUSTER      8
#define FPS_THREADS  128
#define FPS_NWARP    (FPS_THREADS / 32)      // 4
#define NSLOT        (CLUSTER * FPS_NWARP)   // 32
#define PTS_BLK      (NPTS / CLUSTER)        // 4096
#define PPT          (PTS_BLK / FPS_THREADS) // 32
#define NP2          (PPT / 2)               // 16 packed slots

#define CPT        32
#define BQ_THREADS 256
#define CAP        128

#define COMB_ELEMS (BATCH * SPTS * (GRP + 1) * 3)  // 405504
#define FPS_DSMEM  (PTS_BLK * 16)                  // 64KB staging

__device__ float4 g_xyz4[BATCH * NPTS];

// ---------------------------------------------------------------------------
// helpers
// ---------------------------------------------------------------------------
__device__ __forceinline__ unsigned smem_u32(const void* p) {
    unsigned a;
    asm("{ .reg .u64 t; cvta.to.shared.u64 t, %1; cvt.u32.u64 %0, t; }" : "=r"(a) : "l"(p));
    return a;
}
__device__ __forceinline__ unsigned redux_max_u32(unsigned v) {
    unsigned r; asm("redux.sync.max.u32 %0, %1, 0xffffffff;" : "=r"(r) : "r"(v)); return r;
}
__device__ __forceinline__ unsigned redux_min_u32(unsigned v) {
    unsigned r; asm("redux.sync.min.u32 %0, %1, 0xffffffff;" : "=r"(r) : "r"(v)); return r;
}
__device__ __forceinline__ unsigned mapa_u32(unsigned laddr, unsigned rank) {
    unsigned r; asm("mapa.shared::cluster.u32 %0, %1, %2;" : "=r"(r) : "r"(laddr), "r"(rank));
    return r;
}

// packed f32x2 (Blackwell): IEEE rn per component — bit-identical to scalar rn
#define PACK2(d, lo, hi)  asm("mov.b64 %0, {%1, %2};" : "=l"(d) : "f"(lo), "f"(hi))
#define UNPACK2(lo, hi, s) asm("mov.b64 {%0, %1}, %2;" : "=f"(lo), "=f"(hi) : "l"(s))
#define ADD2(d, a, b) asm("add.rn.f32x2 %0, %1, %2;" : "=l"(d) : "l"(a), "l"(b))
#define MUL2(d, a, b) asm("mul.rn.f32x2 %0, %1, %2;" : "=l"(d) : "l"(a), "l"(b))

__device__ __forceinline__ float negf(float a) {
    return __uint_as_float(__float_as_uint(a) ^ 0x80000000u);
}

#define MBAR_INIT(addr, cnt) \
    asm volatile("mbarrier.init.shared.b64 [%0], %1;" :: "r"(addr), "r"(cnt) : "memory")

#define MBAR_EXPECT_TX(addr, bytes) \
    asm volatile("mbarrier.arrive.expect_tx.shared.b64 _, [%0], %1;" \
                 :: "r"(addr), "r"(bytes) : "memory")

// fused data + barrier-signal store to a peer CTA's smem (single fabric hop)
#define ST_ASYNC_U64(rslot, val, rbar) \
    asm volatile("st.async.shared::cluster.mbarrier::complete_tx::bytes.b64 [%0], %1, [%2];" \
                 :: "r"(rslot), "l"(val), "r"(rbar) : "memory")

#define MBAR_WAIT_PARITY_ACQ_CLUSTER(mbar, parity) do {                            \
    unsigned _m = (mbar), _p = (parity), _d;                                       \
    asm volatile("{\n\t.reg .pred p;\n\t"                                          \
        "mbarrier.try_wait.parity.acquire.cluster.shared::cta.b64 p, [%1], %2;\n\t"\
        "selp.b32 %0, 1, 0, p;\n\t}"                                               \
        : "=r"(_d) : "r"(_m), "r"(_p) : "memory");                                 \
    if (!_d) {                                                                     \
        asm volatile("{\n\t.reg .pred P1;\n"                                       \
            "WL_%=:\n\t"                                                           \
            "mbarrier.try_wait.parity.acquire.cluster.shared::cta.b64 P1, [%0], %1;\n\t" \
            "@P1 bra.uni WD_%=;\n\t"                                               \
            "bra.uni WL_%=;\n"                                                     \
            "WD_%=:\n\t}" :: "r"(_m), "r"(_p) : "memory");                         \
    }                                                                              \
} while (0)

#define CLUSTER_SYNC_ASM() do {                                        \
    asm volatile("barrier.cluster.arrive.aligned;" ::: "memory");      \
    asm volatile("barrier.cluster.wait.aligned;" ::: "memory");        \
} while (0)

// ---------------------------------------------------------------------------
// Kernel 0: pack xyz [B,N,3] -> float4
// ---------------------------------------------------------------------------
__global__ void pad_kernel(const float* __restrict__ xyz) {
    int i = blockIdx.x * blockDim.x + threadIdx.x;
    if (i < BATCH * NPTS) {
        g_xyz4[i] = make_float4(xyz[3 * i], xyz[3 * i + 1], xyz[3 * i + 2], 0.f);
    }
}

// ---------------------------------------------------------------------------
// Kernel 1: FPS — flat st.async exchange carrying coords. Publish: lanes 0..7
// read the warp winner's coords from LOCAL staging (uniform broadcast LDS)
// and send {key, xy, zw} (24B) to their target CTA. Receive: slot reduce,
// then winner coords from LOCAL cslot (uniform LDS) — no cross-CTA read in
// the tail. expect_tx = 24B x 32 warps = 768 per phase.
// ---------------------------------------------------------------------------
__global__ void __cluster_dims__(CLUSTER, 1, 1) __launch_bounds__(FPS_THREADS, 1)
fps_kernel(const int* __restrict__ finit, float* __restrict__ out_cent) {
    extern __shared__ float4 stage[];     // [PTS_BLK] this CTA's points
    const int tid  = threadIdx.x;
    const int lane = tid & 31, wid = tid >> 5;
    unsigned rank;
    asm("mov.u32 %0, %%cluster_ctarank;" : "=r"(rank));
    const int b = blockIdx.x / CLUSTER;
    const float4* __restrict__ xb = g_xyz4 + b * NPTS;

    __shared__ unsigned long long cslot[2][NSLOT][3];   // {key, xy, zw} per warp
    __shared__ unsigned long long bars[2];

    if (tid == 0) {
        MBAR_INIT(smem_u32(&bars[0]), 1);
        MBAR_INIT(smem_u32(&bars[1]), 1);
        MBAR_EXPECT_TX(smem_u32(&bars[0]), 24u * NSLOT);
        MBAR_EXPECT_TX(smem_u32(&bars[1]), 24u * NSLOT);
    }

    // stage this CTA's partition into smem
    const int pbase = rank * PTS_BLK;
    for (int i = tid; i < PTS_BLK; i += FPS_THREADS)
        stage[i] = xb[pbase + i];

    __syncthreads();
    CLUSTER_SYNC_ASM();   // barriers + staging visible cluster-wide

    // register-resident points, packed pairs: slot j = points (2j, 2j+1),
    // point i lives at pid0 + i*FPS_THREADS; pid & 4095 = local stage offset
    unsigned long long pxx[NP2], pyy[NP2], pzz[NP2];
    float dd[PPT];
    const int pid0 = pbase + tid;
#pragma unroll
    for (int j = 0; j < NP2; j++) {
        float4 a = stage[tid + (2 * j) * FPS_THREADS];
        float4 c = stage[tid + (2 * j + 1) * FPS_THREADS];
        PACK2(pxx[j], a.x, c.x);
        PACK2(pyy[j], a.y, c.y);
        PACK2(pzz[j], a.z, c.z);
        dd[2 * j] = BIGF; dd[2 * j + 1] = BIGF;
    }

    // hoisted remote addresses: lane r (<8) targets rank r, slot rank*4+wid
    const unsigned lslot0 = smem_u32(&cslot[0][rank * FPS_NWARP + wid][0]);
    const unsigned lslot1 = smem_u32(&cslot[1][rank * FPS_NWARP + wid][0]);
    const unsigned lbar0  = smem_u32(&bars[0]);
    const unsigned lbar1  = smem_u32(&bars[1]);
    const unsigned tr     = (unsigned)(lane & 7);
    const unsigned rslot0 = mapa_u32(lslot0, tr);
    const unsigned rslot1 = mapa_u32(lslot1, tr);
    const unsigned rbar0  = mapa_u32(lbar0, tr);
    const unsigned rbar1  = mapa_u32(lbar1, tr);
    const unsigned stage_base = smem_u32(&stage[0]);

    float4 c0 = xb[finit[b]];
    float cx = c0.x, cy = c0.y, cz = c0.z;

    for (int s = 0; s < SPTS; s++) {
        if (rank == 0 && tid == 0) {
            float* o = out_cent + (size_t)(b * SPTS + s) * 3;
            o[0] = cx; o[1] = cy; o[2] = cz;
        }
        if (s == SPTS - 1) break;

        // ---- packed distance update: (p - c)^2 as p + (-c), exact rn ----
        unsigned long long ncx2, ncy2, ncz2;
        {
            float nx = negf(cx), ny = negf(cy), nz = negf(cz);
            PACK2(ncx2, nx, nx); PACK2(ncy2, ny, ny); PACK2(ncz2, nz, nz);
        }
        float bv = -1.f;
#pragma unroll
        for (int j = 0; j < NP2; j++) {
            unsigned long long dx2, dy2, dz2, s2;
            ADD2(dx2, pxx[j], ncx2);
            ADD2(dy2, pyy[j], ncy2);
            ADD2(dz2, pzz[j], ncz2);
            MUL2(dx2, dx2, dx2);
            MUL2(dy2, dy2, dy2);
            MUL2(dz2, dz2, dz2);
            ADD2(s2, dx2, dy2);
            ADD2(s2, s2, dz2);
            float lo, hi; UNPACK2(lo, hi, s2);
            float n0 = fminf(dd[2 * j], lo);
            float n1 = fminf(dd[2 * j + 1], hi);
            dd[2 * j] = n0; dd[2 * j + 1] = n1;
            bv = fmaxf(bv, n0);
            bv = fmaxf(bv, n1);
        }

        // ---- thread argmax index: equality bitmask (lowest i wins) ----
        unsigned m = 0;
#pragma unroll
        for (int i = 0; i < PPT; i++) m |= (dd[i] == bv) ? (1u << i) : 0u;
        int bi = __ffs(m) - 1;
        unsigned bpid = (unsigned)(pid0 + bi * FPS_THREADS);

        // ---- warp argmax via REDUX (tie -> smaller pid) ----
        unsigned vb   = __float_as_uint(bv);
        unsigned vmax = redux_max_u32(vb);
        unsigned pidw = redux_min_u32((vb == vmax) ? bpid : 0xffffffffu);

        const int bb = s & 1;
        const unsigned ph = (unsigned)((s >> 1) & 1);

        // ---- lanes 0..7: read winner coords from LOCAL staging (uniform
        //      broadcast LDS) and publish {key, xy, zw} to the target CTA ----
        if (lane < CLUSTER) {
            unsigned off = pidw & (PTS_BLK - 1);
            unsigned long long wxy, wzw;
            asm volatile("ld.shared.v2.b64 {%0, %1}, [%2];"
                         : "=l"(wxy), "=l"(wzw) : "r"(stage_base + off * 16u));
            unsigned long long key = ((unsigned long long)vmax << 32) | pidw;
            unsigned rs = bb ? rslot1 : rslot0;
            unsigned rb = bb ? rbar1  : rbar0;
            ST_ASYNC_U64(rs,       key, rb);
            ST_ASYNC_U64(rs + 8u,  wxy, rb);
            ST_ASYNC_U64(rs + 16u, wzw, rb);
        }

        // ---- every warp: wait for all 32 candidates, reduce (1 slot/lane) ----
        const unsigned lbar = bb ? lbar1 : lbar0;
        MBAR_WAIT_PARITY_ACQ_CLUSTER(lbar, ph);

        // re-arm for iteration s+2 (warp0 lane0); safe: any s+2 store is
        // causally after our s+1 publish, which is program-ordered after this.
        if (tid == 0)
            MBAR_EXPECT_TX(lbar, 24u * NSLOT);

        unsigned long long ck = cslot[bb][lane][0];
        unsigned cv  = (unsigned)(ck >> 32);
        unsigned cp  = (unsigned)ck;
        unsigned cvm = redux_max_u32(cv);
        unsigned cpm = redux_min_u32((cv == cvm) ? cp : 0xffffffffu);
        unsigned mk  = __ballot_sync(0xffffffffu, cp == cpm && cv == cvm);
        int src = __ffs(mk) - 1;

        // winner coords from LOCAL cslot (uniform LDS — no cross-CTA read)
        unsigned long long wxy = cslot[bb][src][1];
        unsigned long long wzw = cslot[bb][src][2];
        cx = __uint_as_float((unsigned)wxy);
        cy = __uint_as_float((unsigned)(wxy >> 32));
        cz = __uint_as_float((unsigned)wzw);
    }

    CLUSTER_SYNC_ASM();   // keep smem staging alive until all CTAs done
}

// ---------------------------------------------------------------------------
// Kernel 2: ball query + group — packed f32x2 main loop (proven R13/R14).
// ---------------------------------------------------------------------------
__global__ void __launch_bounds__(BQ_THREADS, 1)
ball_kernel(const float* __restrict__ cent, float* __restrict__ outc) {
    const int b  = blockIdx.x >> 4;
    const int s0 = (blockIdx.x & 15) * CPT;
    const int tid = threadIdx.x;
    const int lane = tid & 31, wid = tid >> 5;

    __shared__ float4 sc[CPT];
    __shared__ int cnt[CPT];
    __shared__ unsigned long long keys[CPT][CAP];
    __shared__ int sel[CPT][GRP];

    if (tid < CPT) {
        cnt[tid] = 0;
        const float* c = cent + (size_t)(b * SPTS + s0 + tid) * 3;
        sc[tid] = make_float4(c[0], c[1], c[2], 0.f);
    }
    __syncthreads();

    unsigned long long ncx2[CPT / 2], ncy2[CPT / 2], ncz2[CPT / 2];
#pragma unroll
    for (int j = 0; j < CPT / 2; j++) {
        float4 a = sc[2 * j], c = sc[2 * j + 1];
        PACK2(ncx2[j], negf(a.x), negf(c.x));
        PACK2(ncy2[j], negf(a.y), negf(c.y));
        PACK2(ncz2[j], negf(a.z), negf(c.z));
    }

    const float4* __restrict__ xb = g_xyz4 + b * NPTS;

    for (int pid = tid; pid < NPTS; pid += BQ_THREADS) {
        float4 p = xb[pid];
        unsigned long long px2, py2, pz2;
        PACK2(px2, p.x, p.x); PACK2(py2, p.y, p.y); PACK2(pz2, p.z, p.z);
#pragma unroll
        for (int j = 0; j < CPT / 2; j++) {
            unsigned long long dx2, dy2, dz2, s2;
            ADD2(dx2, px2, ncx2[j]);
            ADD2(dy2, py2, ncy2[j]);
            ADD2(dz2, pz2, ncz2[j]);
            MUL2(dx2, dx2, dx2);
            MUL2(dy2, dy2, dy2);
            MUL2(dz2, dz2, dz2);
            ADD2(s2, dx2, dy2);
            ADD2(s2, s2, dz2);
            float lo, hi; UNPACK2(lo, hi, s2);
            if (lo <= R2F) {
                int pos = atomicAdd(&cnt[2 * j], 1);
                if (pos < CAP)
                    keys[2 * j][pos] = ((unsigned long long)__float_as_uint(lo) << 32) | (unsigned)pid;
            }
            if (hi <= R2F) {
                int pos = atomicAdd(&cnt[2 * j + 1], 1);
                if (pos < CAP)
                    keys[2 * j + 1][pos] = ((unsigned long long)__float_as_uint(hi) << 32) | (unsigned)pid;
            }
        }
    }
    __syncthreads();

    for (int k = 0; k < CPT / 8; k++) {
        const int c = wid * (CPT / 8) + k;
        const int m = min(cnt[c], CAP);
        const int K = min(m, GRP);

        unsigned long long kk[CAP / 32];
#pragma unroll
        for (int j = 0; j < CAP / 32; j++) {
            int pos = lane + 32 * j;
            kk[j] = (pos < m) ? keys[c][pos] : 0xFFFFFFFFFFFFFFFFull;
        }
        for (int t = 0; t < K; t++) {
            unsigned long long lmin = kk[0];
#pragma unroll
            for (int j = 1; j < CAP / 32; j++) lmin = (kk[j] < lmin) ? kk[j] : lmin;
            unsigned ld = (unsigned)(lmin >> 32);
            unsigned lp = (unsigned)lmin;
            unsigned dmin = redux_min_u32(ld);
            unsigned pidm = redux_min_u32((ld == dmin) ? lp : 0xffffffffu);
            unsigned long long lm = ((unsigned long long)dmin << 32) | pidm;
#pragma unroll
            for (int j = 0; j < CAP / 32; j++) if (kk[j] == lm) kk[j] = 0xFFFFFFFFFFFFFFFFull;
            if (lane == 0) sel[c][t] = (int)pidm;
        }

        float ccx, ccy, ccz;
        { float4 t4 = sc[c]; ccx = t4.x; ccy = t4.y; ccz = t4.z; }
        int need = GRP - K;
        int base = 0;
        while (need > 0) {
            int id = base + lane;
            bool oor = false;
            if (id < NPTS) {
                float4 p = xb[id];
                float dx = p.x - ccx, dy = p.y - ccy, dz = p.z - ccz;
                float sq = __fadd_rn(__fadd_rn(__fmul_rn(dx, dx), __fmul_rn(dy, dy)),
                                     __fmul_rn(dz, dz));
                oor = (sq > R2F);
            }
            unsigned msk = __ballot_sync(0xffffffffu, oor);
            int r = __popc(msk & ((1u << lane) - 1u));
            if (oor && r < need) sel[c][GRP - need + r] = id;
            int take = min(__popc(msk), need);
            need -= take;
            base += 32;
        }
    }
    __syncthreads();

    for (int k = 0; k < CPT / 8; k++) {
        const int c = wid * (CPT / 8) + k;
        const int s = s0 + c;
        float4 cc = sc[c];
        float* ob = outc + (size_t)((b * SPTS + s) * (GRP + 1)) * 3;
        if (lane == 0) { ob[0] = cc.x; ob[1] = cc.y; ob[2] = cc.z; }
        int idx = sel[c][lane];
        float4 p = xb[idx];
        float* og = ob + (size_t)(1 + lane) * 3;
        og[0] = p.x - cc.x; og[1] = p.y - cc.y; og[2] = p.z - cc.z;
    }
}

// ---------------------------------------------------------------------------
extern "C" void kernel_launch(void* const* d_in, const int* in_sizes, int n_in,
                              void* d_out, int out_size) {
    const float* xyz   = (const float*)d_in[0];
    const int*   finit = (const int*)d_in[1];
    float* out  = (float*)d_out;
    float* comb = out;                 // [B,S,33,3]
    float* cent = out + COMB_ELEMS;    // [B,S,3]

    // allow 64KB dynamic smem for the FPS staging (idempotent, not an alloc)
    cudaFuncSetAttribute(fps_kernel, cudaFuncAttributeMaxDynamicSharedMemorySize,
                         FPS_DSMEM);

    pad_kernel<<<(BATCH * NPTS + 255) / 256, 256>>>(xyz);
    fps_kernel<<<BATCH * CLUSTER, FPS_THREADS, FPS_DSMEM>>>(finit, cent);
    ball_kernel<<<BATCH * (SPTS / CPT), BQ_THREADS>>>(cent, comb);
}

// round 16
// speedup vs baseline: 1.3125x; 1.0137x over previous
#include <cuda_runtime.h>
#include <cstdint>

#define BATCH 8
#define NPTS  32768
#define SPTS  512
#define GRP   32
#define BIGF  1e10f
#define R2F   0.04f

#define CLUSTER      8
#define FPS_THREADS  128
#define FPS_NWARP    (FPS_THREADS / 32)      // 4
#define NSLOT        (CLUSTER * FPS_NWARP)   // 32
#define PTS_BLK      (NPTS / CLUSTER)        // 4096
#define PPT          (PTS_BLK / FPS_THREADS) // 32
#define NP2          (PPT / 2)               // 16 packed slots

#define CPT        32
#define BQ_THREADS 256
#define CAP        128

#define COMB_ELEMS (BATCH * SPTS * (GRP + 1) * 3)  // 405504
#define FPS_DSMEM  (PTS_BLK * 16)                  // 64KB staging

__device__ float4 g_xyz4[BATCH * NPTS];

// ---------------------------------------------------------------------------
// helpers
// ---------------------------------------------------------------------------
__device__ __forceinline__ unsigned smem_u32(const void* p) {
    unsigned a;
    asm("{ .reg .u64 t; cvta.to.shared.u64 t, %1; cvt.u32.u64 %0, t; }" : "=r"(a) : "l"(p));
    return a;
}
__device__ __forceinline__ unsigned redux_max_u32(unsigned v) {
    unsigned r; asm("redux.sync.max.u32 %0, %1, 0xffffffff;" : "=r"(r) : "r"(v)); return r;
}
__device__ __forceinline__ unsigned redux_min_u32(unsigned v) {
    unsigned r; asm("redux.sync.min.u32 %0, %1, 0xffffffff;" : "=r"(r) : "r"(v)); return r;
}
__device__ __forceinline__ unsigned mapa_u32(unsigned laddr, unsigned rank) {
    unsigned r; asm("mapa.shared::cluster.u32 %0, %1, %2;" : "=r"(r) : "r"(laddr), "r"(rank));
    return r;
}

// packed f32x2 (Blackwell): IEEE rn per component — bit-identical to scalar rn
#define PACK2(d, lo, hi)  asm("mov.b64 %0, {%1, %2};" : "=l"(d) : "f"(lo), "f"(hi))
#define UNPACK2(lo, hi, s) asm("mov.b64 {%0, %1}, %2;" : "=f"(lo), "=f"(hi) : "l"(s))
#define ADD2(d, a, b) asm("add.rn.f32x2 %0, %1, %2;" : "=l"(d) : "l"(a), "l"(b))
#define MUL2(d, a, b) asm("mul.rn.f32x2 %0, %1, %2;" : "=l"(d) : "l"(a), "l"(b))

__device__ __forceinline__ float negf(float a) {
    return __uint_as_float(__float_as_uint(a) ^ 0x80000000u);
}

#define MBAR_INIT(addr, cnt) \
    asm volatile("mbarrier.init.shared.b64 [%0], %1;" :: "r"(addr), "r"(cnt) : "memory")

#define MBAR_EXPECT_TX(addr, bytes) \
    asm volatile("mbarrier.arrive.expect_tx.shared.b64 _, [%0], %1;" \
                 :: "r"(addr), "r"(bytes) : "memory")

// fused data + barrier-signal stores to a peer CTA's smem (single fabric hop)
#define ST_ASYNC_U64(rslot, val, rbar) \
    asm volatile("st.async.shared::cluster.mbarrier::complete_tx::bytes.b64 [%0], %1, [%2];" \
                 :: "r"(rslot), "l"(val), "r"(rbar) : "memory")

#define ST_ASYNC_V2U64(rslot, v0, v1, rbar) \
    asm volatile("st.async.shared::cluster.mbarrier::complete_tx::bytes.v2.b64 [%0], {%1, %2}, [%3];" \
                 :: "r"(rslot), "l"(v0), "l"(v1), "r"(rbar) : "memory")

#define MBAR_WAIT_PARITY_ACQ_CLUSTER(mbar, parity) do {                            \
    unsigned _m = (mbar), _p = (parity), _d;                                       \
    asm volatile("{\n\t.reg .pred p;\n\t"                                          \
        "mbarrier.try_wait.parity.acquire.cluster.shared::cta.b64 p, [%1], %2;\n\t"\
        "selp.b32 %0, 1, 0, p;\n\t}"                                               \
        : "=r"(_d) : "r"(_m), "r"(_p) : "memory");                                 \
    if (!_d) {                                                                     \
        asm volatile("{\n\t.reg .pred P1;\n"                                       \
            "WL_%=:\n\t"                                                           \
            "mbarrier.try_wait.parity.acquire.cluster.shared::cta.b64 P1, [%0], %1;\n\t" \
            "@P1 bra.uni WD_%=;\n\t"                                               \
            "bra.uni WL_%=;\n"                                                     \
            "WD_%=:\n\t}" :: "r"(_m), "r"(_p) : "memory");                         \
    }                                                                              \
} while (0)

#define CLUSTER_SYNC_ASM() do {                                        \
    asm volatile("barrier.cluster.arrive.aligned;" ::: "memory");      \
    asm volatile("barrier.cluster.wait.aligned;" ::: "memory");        \
} while (0)

// ---------------------------------------------------------------------------
// Kernel 0: pack xyz [B,N,3] -> float4
// ---------------------------------------------------------------------------
__global__ void pad_kernel(const float* __restrict__ xyz) {
    int i = blockIdx.x * blockDim.x + threadIdx.x;
    if (i < BATCH * NPTS) {
        g_xyz4[i] = make_float4(xyz[3 * i], xyz[3 * i + 1], xyz[3 * i + 2], 0.f);
    }
}

// ---------------------------------------------------------------------------
// Kernel 1: FPS — R15 structure (flat st.async exchange carrying coords), but
// the 24B payload ships as TWO st.async (v2.b64 {key,xy} + b64 zw) instead of
// three: 64 barrier-tx updates per phase instead of 96. expect_tx = 768.
// Slot: 32B stride, 16B-aligned: [key, xy, zw, pad].
// ---------------------------------------------------------------------------
struct __align__(16) XSlot { unsigned long long key, xy, zw, pad; };

__global__ void __cluster_dims__(CLUSTER, 1, 1) __launch_bounds__(FPS_THREADS, 1)
fps_kernel(const int* __restrict__ finit, float* __restrict__ out_cent) {
    extern __shared__ float4 stage[];     // [PTS_BLK] this CTA's points
    const int tid  = threadIdx.x;
    const int lane = tid & 31, wid = tid >> 5;
    unsigned rank;
    asm("mov.u32 %0, %%cluster_ctarank;" : "=r"(rank));
    const int b = blockIdx.x / CLUSTER;
    const float4* __restrict__ xb = g_xyz4 + b * NPTS;

    __shared__ XSlot cslot[2][NSLOT];     // {key, xy, zw} per warp (dbl buf)
    __shared__ unsigned long long bars[2];

    if (tid == 0) {
        MBAR_INIT(smem_u32(&bars[0]), 1);
        MBAR_INIT(smem_u32(&bars[1]), 1);
        MBAR_EXPECT_TX(smem_u32(&bars[0]), 24u * NSLOT);
        MBAR_EXPECT_TX(smem_u32(&bars[1]), 24u * NSLOT);
    }

    // stage this CTA's partition into smem
    const int pbase = rank * PTS_BLK;
    for (int i = tid; i < PTS_BLK; i += FPS_THREADS)
        stage[i] = xb[pbase + i];

    __syncthreads();
    CLUSTER_SYNC_ASM();   // barriers + staging visible cluster-wide

    // register-resident points, packed pairs: slot j = points (2j, 2j+1),
    // point i lives at pid0 + i*FPS_THREADS; pid & 4095 = local stage offset
    unsigned long long pxx[NP2], pyy[NP2], pzz[NP2];
    float dd[PPT];
    const int pid0 = pbase + tid;
#pragma unroll
    for (int j = 0; j < NP2; j++) {
        float4 a = stage[tid + (2 * j) * FPS_THREADS];
        float4 c = stage[tid + (2 * j + 1) * FPS_THREADS];
        PACK2(pxx[j], a.x, c.x);
        PACK2(pyy[j], a.y, c.y);
        PACK2(pzz[j], a.z, c.z);
        dd[2 * j] = BIGF; dd[2 * j + 1] = BIGF;
    }

    // hoisted remote addresses: lane r (<8) targets rank r, slot rank*4+wid
    const unsigned lslot0 = smem_u32(&cslot[0][rank * FPS_NWARP + wid]);
    const unsigned lslot1 = smem_u32(&cslot[1][rank * FPS_NWARP + wid]);
    const unsigned lbar0  = smem_u32(&bars[0]);
    const unsigned lbar1  = smem_u32(&bars[1]);
    const unsigned tr     = (unsigned)(lane & 7);
    const unsigned rslot0 = mapa_u32(lslot0, tr);
    const unsigned rslot1 = mapa_u32(lslot1, tr);
    const unsigned rbar0  = mapa_u32(lbar0, tr);
    const unsigned rbar1  = mapa_u32(lbar1, tr);
    const unsigned stage_base = smem_u32(&stage[0]);

    float4 c0 = xb[finit[b]];
    float cx = c0.x, cy = c0.y, cz = c0.z;

    for (int s = 0; s < SPTS; s++) {
        if (rank == 0 && tid == 0) {
            float* o = out_cent + (size_t)(b * SPTS + s) * 3;
            o[0] = cx; o[1] = cy; o[2] = cz;
        }
        if (s == SPTS - 1) break;

        // ---- packed distance update: (p - c)^2 as p + (-c), exact rn ----
        unsigned long long ncx2, ncy2, ncz2;
        {
            float nx = negf(cx), ny = negf(cy), nz = negf(cz);
            PACK2(ncx2, nx, nx); PACK2(ncy2, ny, ny); PACK2(ncz2, nz, nz);
        }
        float bv = -1.f;
#pragma unroll
        for (int j = 0; j < NP2; j++) {
            unsigned long long dx2, dy2, dz2, s2;
            ADD2(dx2, pxx[j], ncx2);
            ADD2(dy2, pyy[j], ncy2);
            ADD2(dz2, pzz[j], ncz2);
            MUL2(dx2, dx2, dx2);
            MUL2(dy2, dy2, dy2);
            MUL2(dz2, dz2, dz2);
            ADD2(s2, dx2, dy2);
            ADD2(s2, s2, dz2);
            float lo, hi; UNPACK2(lo, hi, s2);
            float n0 = fminf(dd[2 * j], lo);
            float n1 = fminf(dd[2 * j + 1], hi);
            dd[2 * j] = n0; dd[2 * j + 1] = n1;
            bv = fmaxf(bv, n0);
            bv = fmaxf(bv, n1);
        }

        // ---- thread argmax index: equality bitmask (lowest i wins) ----
        unsigned m = 0;
#pragma unroll
        for (int i = 0; i < PPT; i++) m |= (dd[i] == bv) ? (1u << i) : 0u;
        int bi = __ffs(m) - 1;
        unsigned bpid = (unsigned)(pid0 + bi * FPS_THREADS);

        // ---- warp argmax via REDUX (tie -> smaller pid) ----
        unsigned vb   = __float_as_uint(bv);
        unsigned vmax = redux_max_u32(vb);
        unsigned pidw = redux_min_u32((vb == vmax) ? bpid : 0xffffffffu);

        const int bb = s & 1;
        const unsigned ph = (unsigned)((s >> 1) & 1);

        // ---- lanes 0..7: winner coords via uniform broadcast LDS, publish
        //      {key, xy} (v2.b64) + zw (b64) — two tx per target ----
        if (lane < CLUSTER) {
            unsigned off = pidw & (PTS_BLK - 1);
            unsigned long long wxy, wzw;
            asm volatile("ld.shared.v2.b64 {%0, %1}, [%2];"
                         : "=l"(wxy), "=l"(wzw) : "r"(stage_base + off * 16u));
            unsigned long long key = ((unsigned long long)vmax << 32) | pidw;
            unsigned rs = bb ? rslot1 : rslot0;
            unsigned rb = bb ? rbar1  : rbar0;
            ST_ASYNC_V2U64(rs,      key, wxy, rb);
            ST_ASYNC_U64(rs + 16u,  wzw, rb);
        }

        // ---- every warp: wait for all 32 candidates, reduce (1 slot/lane) ----
        const unsigned lbar = bb ? lbar1 : lbar0;
        MBAR_WAIT_PARITY_ACQ_CLUSTER(lbar, ph);

        // re-arm for iteration s+2 (warp0 lane0); safe: any s+2 store is
        // causally after our s+1 publish, which is program-ordered after this.
        if (tid == 0)
            MBAR_EXPECT_TX(lbar, 24u * NSLOT);

        unsigned long long ck = cslot[bb][lane].key;
        unsigned cv  = (unsigned)(ck >> 32);
        unsigned cp  = (unsigned)ck;
        unsigned cvm = redux_max_u32(cv);
        unsigned cpm = redux_min_u32((cv == cvm) ? cp : 0xffffffffu);
        unsigned mk  = __ballot_sync(0xffffffffu, cp == cpm && cv == cvm);
        int src = __ffs(mk) - 1;

        // winner coords from LOCAL cslot (uniform LDS — no cross-CTA read)
        unsigned long long wxy = cslot[bb][src].xy;
        unsigned long long wzw = cslot[bb][src].zw;
        cx = __uint_as_float((unsigned)wxy);
        cy = __uint_as_float((unsigned)(wxy >> 32));
        cz = __uint_as_float((unsigned)wzw);
    }

    CLUSTER_SYNC_ASM();   // keep smem staging alive until all CTAs done
}

// ---------------------------------------------------------------------------
// Kernel 2: ball query + group — packed f32x2 main loop (proven R13-R15).
// ---------------------------------------------------------------------------
__global__ void __launch_bounds__(BQ_THREADS, 1)
ball_kernel(const float* __restrict__ cent, float* __restrict__ outc) {
    const int b  = blockIdx.x >> 4;
    const int s0 = (blockIdx.x & 15) * CPT;
    const int tid = threadIdx.x;
    const int lane = tid & 31, wid = tid >> 5;

    __shared__ float4 sc[CPT];
    __shared__ int cnt[CPT];
    __shared__ unsigned long long keys[CPT][CAP];
    __shared__ int sel[CPT][GRP];

    if (tid < CPT) {
        cnt[tid] = 0;
        const float* c = cent + (size_t)(b * SPTS + s0 + tid) * 3;
        sc[tid] = make_float4(c[0], c[1], c[2], 0.f);
    }
    __syncthreads();

    unsigned long long ncx2[CPT / 2], ncy2[CPT / 2], ncz2[CPT / 2];
#pragma unroll
    for (int j = 0; j < CPT / 2; j++) {
        float4 a = sc[2 * j], c = sc[2 * j + 1];
        PACK2(ncx2[j], negf(a.x), negf(c.x));
        PACK2(ncy2[j], negf(a.y), negf(c.y));
        PACK2(ncz2[j], negf(a.z), negf(c.z));
    }

    const float4* __restrict__ xb = g_xyz4 + b * NPTS;

    for (int pid = tid; pid < NPTS; pid += BQ_THREADS) {
        float4 p = xb[pid];
        unsigned long long px2, py2, pz2;
        PACK2(px2, p.x, p.x); PACK2(py2, p.y, p.y); PACK2(pz2, p.z, p.z);
#pragma unroll
        for (int j = 0; j < CPT / 2; j++) {
            unsigned long long dx2, dy2, dz2, s2;
            ADD2(dx2, px2, ncx2[j]);
            ADD2(dy2, py2, ncy2[j]);
            ADD2(dz2, pz2, ncz2[j]);
            MUL2(dx2, dx2, dx2);
            MUL2(dy2, dy2, dy2);
            MUL2(dz2, dz2, dz2);
            ADD2(s2, dx2, dy2);
            ADD2(s2, s2, dz2);
            float lo, hi; UNPACK2(lo, hi, s2);
            if (lo <= R2F) {
                int pos = atomicAdd(&cnt[2 * j], 1);
                if (pos < CAP)
                    keys[2 * j][pos] = ((unsigned long long)__float_as_uint(lo) << 32) | (unsigned)pid;
            }
            if (hi <= R2F) {
                int pos = atomicAdd(&cnt[2 * j + 1], 1);
                if (pos < CAP)
                    keys[2 * j + 1][pos] = ((unsigned long long)__float_as_uint(hi) << 32) | (unsigned)pid;
            }
        }
    }
    __syncthreads();

    for (int k = 0; k < CPT / 8; k++) {
        const int c = wid * (CPT / 8) + k;
        const int m = min(cnt[c], CAP);
        const int K = min(m, GRP);

        unsigned long long kk[CAP / 32];
#pragma unroll
        for (int j = 0; j < CAP / 32; j++) {
            int pos = lane + 32 * j;
            kk[j] = (pos < m) ? keys[c][pos] : 0xFFFFFFFFFFFFFFFFull;
        }
        for (int t = 0; t < K; t++) {
            unsigned long long lmin = kk[0];
#pragma unroll
            for (int j = 1; j < CAP / 32; j++) lmin = (kk[j] < lmin) ? kk[j] : lmin;
            unsigned ld = (unsigned)(lmin >> 32);
            unsigned lp = (unsigned)lmin;
            unsigned dmin = redux_min_u32(ld);
            unsigned pidm = redux_min_u32((ld == dmin) ? lp : 0xffffffffu);
            unsigned long long lm = ((unsigned long long)dmin << 32) | pidm;
#pragma unroll
            for (int j = 0; j < CAP / 32; j++) if (kk[j] == lm) kk[j] = 0xFFFFFFFFFFFFFFFFull;
            if (lane == 0) sel[c][t] = (int)pidm;
        }

        float ccx, ccy, ccz;
        { float4 t4 = sc[c]; ccx = t4.x; ccy = t4.y; ccz = t4.z; }
        int need = GRP - K;
        int base = 0;
        while (need > 0) {
            int id = base + lane;
            bool oor = false;
            if (id < NPTS) {
                float4 p = xb[id];
                float dx = p.x - ccx, dy = p.y - ccy, dz = p.z - ccz;
                float sq = __fadd_rn(__fadd_rn(__fmul_rn(dx, dx), __fmul_rn(dy, dy)),
                                     __fmul_rn(dz, dz));
                oor = (sq > R2F);
            }
            unsigned msk = __ballot_sync(0xffffffffu, oor);
            int r = __popc(msk & ((1u << lane) - 1u));
            if (oor && r < need) sel[c][GRP - need + r] = id;
            int take = min(__popc(msk), need);
            need -= take;
            base += 32;
        }
    }
    __syncthreads();

    for (int k = 0; k < CPT / 8; k++) {
        const int c = wid * (CPT / 8) + k;
        const int s = s0 + c;
        float4 cc = sc[c];
        float* ob = outc + (size_t)((b * SPTS + s) * (GRP + 1)) * 3;
        if (lane == 0) { ob[0] = cc.x; ob[1] = cc.y; ob[2] = cc.z; }
        int idx = sel[c][lane];
        float4 p = xb[idx];
        float* og = ob + (size_t)(1 + lane) * 3;
        og[0] = p.x - cc.x; og[1] = p.y - cc.y; og[2] = p.z - cc.z;
    }
}

// ---------------------------------------------------------------------------
extern "C" void kernel_launch(void* const* d_in, const int* in_sizes, int n_in,
                              void* d_out, int out_size) {
    const float* xyz   = (const float*)d_in[0];
    const int*   finit = (const int*)d_in[1];
    float* out  = (float*)d_out;
    float* comb = out;                 // [B,S,33,3]
    float* cent = out + COMB_ELEMS;    // [B,S,3]

    // allow 64KB dynamic smem for the FPS staging (idempotent, not an alloc)
    cudaFuncSetAttribute(fps_kernel, cudaFuncAttributeMaxDynamicSharedMemorySize,
                         FPS_DSMEM);

    pad_kernel<<<(BATCH * NPTS + 255) / 256, 256>>>(xyz);
    fps_kernel<<<BATCH * CLUSTER, FPS_THREADS, FPS_DSMEM>>>(finit, cent);
    ball_kernel<<<BATCH * (SPTS / CPT), BQ_THREADS>>>(cent, comb);
}